// round 1
// baseline (speedup 1.0000x reference)
#include <cuda_runtime.h>
#include <cstdint>

// Problem constants: B=2, T=8192, D=2048, W=128
#define BATCH 2
#define SEQ   8192
#define DIM   2048
#define WIN   128
#define NBLK  64              // SEQ / WIN per batch
#define ROWS  16384           // BATCH * SEQ
#define QKVN  6144            // 3 * DIM

// Scratch (device globals are the sanctioned alloc-free workaround)
__device__ float g_qkv[(size_t)ROWS * QKVN];        // 402 MB: [row][q(2048) k(2048) v(2048)]
__device__ float g_attn[(size_t)BATCH * NBLK * 128 * 256]; // 16.8 MB
__device__ float g_ao[(size_t)ROWS * DIM];          // 134 MB

// ---------------------------------------------------------------------------
// helpers
// ---------------------------------------------------------------------------
__device__ __forceinline__ float cvt_tf32(float x) {
    uint32_t u;
    asm("cvt.rna.tf32.f32 %0, %1;" : "=r"(u) : "f"(x));
    return __uint_as_float(u);
}

__device__ __forceinline__ void mma_tf32(float& d0, float& d1, float& d2, float& d3,
                                         float a0, float a1, float a2, float a3,
                                         float b0, float b1) {
    asm volatile(
        "mma.sync.aligned.m16n8k8.row.col.f32.tf32.tf32.f32 "
        "{%0,%1,%2,%3}, {%4,%5,%6,%7}, {%8,%9}, {%0,%1,%2,%3};\n"
        : "+f"(d0), "+f"(d1), "+f"(d2), "+f"(d3)
        : "r"(__float_as_uint(a0)), "r"(__float_as_uint(a1)),
          "r"(__float_as_uint(a2)), "r"(__float_as_uint(a3)),
          "r"(__float_as_uint(b0)), "r"(__float_as_uint(b1)));
}

// ---------------------------------------------------------------------------
// Generic NT GEMM: C[M,N] = A[M,K] @ B[N,K]^T  (both row-major, K contiguous)
// CTA tile 128x128, K-tile 32, 256 threads (8 warps: 4 along M x 2 along N).
// ---------------------------------------------------------------------------
__global__ __launch_bounds__(256, 1)
void gemm_nt_kernel(const float* __restrict__ A, const float* __restrict__ B,
                    float* __restrict__ C, int M, int N, int K) {
    __shared__ float As[128][36];   // +4 pad: bank = (4r + c) % 32, conflict-free
    __shared__ float Bs[128][36];

    const int tid  = threadIdx.x;
    const int warp = tid >> 5, lane = tid & 31;
    const int wm = (warp & 3) << 5;   // 0,32,64,96
    const int wn = (warp >> 2) << 6;  // 0,64
    const int g  = lane >> 2, tg = lane & 3;
    const int lr = tid >> 3;          // 0..31
    const int lc = (tid & 7) << 2;    // 0..28 step 4

    const float* Ab = A + (size_t)(blockIdx.y * 128 + lr) * K + lc;
    const float* Bb = B + (size_t)(blockIdx.x * 128 + lr) * K + lc;

    float acc[2][8][4];
    #pragma unroll
    for (int i = 0; i < 2; i++)
        #pragma unroll
        for (int j = 0; j < 8; j++)
            #pragma unroll
            for (int q = 0; q < 4; q++) acc[i][j][q] = 0.f;

    float4 ra[4], rb[4];
    #pragma unroll
    for (int i = 0; i < 4; i++) {
        ra[i] = *(const float4*)(Ab + (size_t)(i * 32) * K);
        rb[i] = *(const float4*)(Bb + (size_t)(i * 32) * K);
    }

    for (int kt = 0; kt < K; kt += 32) {
        #pragma unroll
        for (int i = 0; i < 4; i++) {
            As[lr + i * 32][lc + 0] = cvt_tf32(ra[i].x);
            As[lr + i * 32][lc + 1] = cvt_tf32(ra[i].y);
            As[lr + i * 32][lc + 2] = cvt_tf32(ra[i].z);
            As[lr + i * 32][lc + 3] = cvt_tf32(ra[i].w);
            Bs[lr + i * 32][lc + 0] = cvt_tf32(rb[i].x);
            Bs[lr + i * 32][lc + 1] = cvt_tf32(rb[i].y);
            Bs[lr + i * 32][lc + 2] = cvt_tf32(rb[i].z);
            Bs[lr + i * 32][lc + 3] = cvt_tf32(rb[i].w);
        }
        __syncthreads();
        if (kt + 32 < K) {
            #pragma unroll
            for (int i = 0; i < 4; i++) {
                ra[i] = *(const float4*)(Ab + (size_t)(i * 32) * K + (kt + 32));
                rb[i] = *(const float4*)(Bb + (size_t)(i * 32) * K + (kt + 32));
            }
        }
        #pragma unroll
        for (int ks = 0; ks < 4; ks++) {
            const int k0 = ks * 8;
            float a[2][4], bb[8][2];
            #pragma unroll
            for (int mf = 0; mf < 2; mf++) {
                const int r = wm + mf * 16 + g;
                a[mf][0] = As[r][k0 + tg];
                a[mf][1] = As[r + 8][k0 + tg];
                a[mf][2] = As[r][k0 + tg + 4];
                a[mf][3] = As[r + 8][k0 + tg + 4];
            }
            #pragma unroll
            for (int nf = 0; nf < 8; nf++) {
                const int r = wn + nf * 8 + g;
                bb[nf][0] = Bs[r][k0 + tg];
                bb[nf][1] = Bs[r][k0 + tg + 4];
            }
            #pragma unroll
            for (int mf = 0; mf < 2; mf++)
                #pragma unroll
                for (int nf = 0; nf < 8; nf++)
                    mma_tf32(acc[mf][nf][0], acc[mf][nf][1], acc[mf][nf][2], acc[mf][nf][3],
                             a[mf][0], a[mf][1], a[mf][2], a[mf][3],
                             bb[nf][0], bb[nf][1]);
        }
        __syncthreads();
    }

    #pragma unroll
    for (int mf = 0; mf < 2; mf++) {
        #pragma unroll
        for (int nf = 0; nf < 8; nf++) {
            const int row = blockIdx.y * 128 + wm + mf * 16 + g;
            const int col = blockIdx.x * 128 + wn + nf * 8 + (tg << 1);
            *(float2*)(C + (size_t)row * N + col) =
                make_float2(acc[mf][nf][0], acc[mf][nf][1]);
            *(float2*)(C + (size_t)(row + 8) * N + col) =
                make_float2(acc[mf][nf][2], acc[mf][nf][3]);
        }
    }
}

// ---------------------------------------------------------------------------
// sim kernel: for block (b,w), half h: sim[128,128] = q_blk @ k_half^T over K=2048
// then mask + (1/W scale) + relu^2, write to g_attn[blk][i][h*128 + j].
// half 0 = previous key block (valid iff w>0, keep iff i<=j)
// half 1 = current  key block (keep iff i>=j)
// ---------------------------------------------------------------------------
__global__ __launch_bounds__(256, 1)
void attn_sim_kernel(const float* __restrict__ qkv, float* __restrict__ attnOut) {
    const int half = blockIdx.x, w = blockIdx.y, b = blockIdx.z;
    __shared__ float As[128][36];
    __shared__ float Bs[128][36];

    const int tid  = threadIdx.x;
    const int warp = tid >> 5, lane = tid & 31;
    const int wm = (warp & 3) << 5;
    const int wn = (warp >> 2) << 6;
    const int g  = lane >> 2, tg = lane & 3;
    const int lr = tid >> 3;
    const int lc = (tid & 7) << 2;

    const int kblk = (half == 0) ? (w > 0 ? w - 1 : 0) : w;  // w==0,half==0: dummy (fully masked)
    const float* Ab = qkv + (size_t)(b * SEQ + w * 128 + lr) * QKVN + lc;           // q
    const float* Bb = qkv + (size_t)(b * SEQ + kblk * 128 + lr) * QKVN + 2048 + lc; // k

    float acc[2][8][4];
    #pragma unroll
    for (int i = 0; i < 2; i++)
        #pragma unroll
        for (int j = 0; j < 8; j++)
            #pragma unroll
            for (int q = 0; q < 4; q++) acc[i][j][q] = 0.f;

    float4 ra[4], rb[4];
    #pragma unroll
    for (int i = 0; i < 4; i++) {
        ra[i] = *(const float4*)(Ab + (size_t)(i * 32) * QKVN);
        rb[i] = *(const float4*)(Bb + (size_t)(i * 32) * QKVN);
    }

    for (int kt = 0; kt < DIM; kt += 32) {
        #pragma unroll
        for (int i = 0; i < 4; i++) {
            As[lr + i * 32][lc + 0] = cvt_tf32(ra[i].x);
            As[lr + i * 32][lc + 1] = cvt_tf32(ra[i].y);
            As[lr + i * 32][lc + 2] = cvt_tf32(ra[i].z);
            As[lr + i * 32][lc + 3] = cvt_tf32(ra[i].w);
            Bs[lr + i * 32][lc + 0] = cvt_tf32(rb[i].x);
            Bs[lr + i * 32][lc + 1] = cvt_tf32(rb[i].y);
            Bs[lr + i * 32][lc + 2] = cvt_tf32(rb[i].z);
            Bs[lr + i * 32][lc + 3] = cvt_tf32(rb[i].w);
        }
        __syncthreads();
        if (kt + 32 < DIM) {
            #pragma unroll
            for (int i = 0; i < 4; i++) {
                ra[i] = *(const float4*)(Ab + (size_t)(i * 32) * QKVN + (kt + 32));
                rb[i] = *(const float4*)(Bb + (size_t)(i * 32) * QKVN + (kt + 32));
            }
        }
        #pragma unroll
        for (int ks = 0; ks < 4; ks++) {
            const int k0 = ks * 8;
            float a[2][4], bb[8][2];
            #pragma unroll
            for (int mf = 0; mf < 2; mf++) {
                const int r = wm + mf * 16 + g;
                a[mf][0] = As[r][k0 + tg];
                a[mf][1] = As[r + 8][k0 + tg];
                a[mf][2] = As[r][k0 + tg + 4];
                a[mf][3] = As[r + 8][k0 + tg + 4];
            }
            #pragma unroll
            for (int nf = 0; nf < 8; nf++) {
                const int r = wn + nf * 8 + g;
                bb[nf][0] = Bs[r][k0 + tg];
                bb[nf][1] = Bs[r][k0 + tg + 4];
            }
            #pragma unroll
            for (int mf = 0; mf < 2; mf++)
                #pragma unroll
                for (int nf = 0; nf < 8; nf++)
                    mma_tf32(acc[mf][nf][0], acc[mf][nf][1], acc[mf][nf][2], acc[mf][nf][3],
                             a[mf][0], a[mf][1], a[mf][2], a[mf][3],
                             bb[nf][0], bb[nf][1]);
        }
        __syncthreads();
    }

    const bool halfvalid = (half == 1) || (w > 0);
    const float inv_w = 1.0f / (float)WIN;
    float* Cb = attnOut + ((size_t)(b * NBLK + w) * 128) * 256 + half * 128;

    #pragma unroll
    for (int mf = 0; mf < 2; mf++) {
        #pragma unroll
        for (int nf = 0; nf < 8; nf++) {
            const int qi0 = wm + mf * 16 + g;
            const int kj  = wn + nf * 8 + (tg << 1);
            #pragma unroll
            for (int rr = 0; rr < 2; rr++) {
                const int qi = qi0 + rr * 8;
                float2 v;
                float s0 = acc[mf][nf][rr * 2 + 0] * inv_w;
                float s1 = acc[mf][nf][rr * 2 + 1] * inv_w;
                bool k0 = halfvalid && ((half == 0) ? (qi <= kj)     : (qi >= kj));
                bool k1 = halfvalid && ((half == 0) ? (qi <= kj + 1) : (qi >= kj + 1));
                float r0 = k0 ? fmaxf(s0, 0.f) : 0.f;
                float r1 = k1 ? fmaxf(s1, 0.f) : 0.f;
                v.x = r0 * r0;
                v.y = r1 * r1;
                *(float2*)(Cb + (size_t)qi * 256 + kj) = v;
            }
        }
    }
}

// ---------------------------------------------------------------------------
// PV kernel: out_blk[128, ntile*128 .. +128] = attn[128,256] @ V2[256, ...]
// V2 rows 0..127 = v of previous block, 128..255 = v of current block.
// B is staged k-major: Bs[k][n], stride 136 (bank = 8k+n, conflict-free).
// ---------------------------------------------------------------------------
__global__ __launch_bounds__(256, 1)
void attn_pv_kernel(const float* __restrict__ qkv, const float* __restrict__ attn,
                    float* __restrict__ ao) {
    const int nb = blockIdx.x * 128, w = blockIdx.y, b = blockIdx.z;
    __shared__ float As[128][36];
    __shared__ float Bs[32][136];

    const int tid  = threadIdx.x;
    const int warp = tid >> 5, lane = tid & 31;
    const int wm = (warp & 3) << 5;
    const int wn = (warp >> 2) << 6;
    const int g  = lane >> 2, tg = lane & 3;
    const int lr = tid >> 3;
    const int lc = (tid & 7) << 2;

    const int prevblk = (w > 0) ? w - 1 : 0;  // w==0: attn[:, :128]==0, rows are dummies
    const float* Ab = attn + ((size_t)(b * NBLK + w) * 128 + lr) * 256 + lc;

    float acc[2][8][4];
    #pragma unroll
    for (int i = 0; i < 2; i++)
        #pragma unroll
        for (int j = 0; j < 8; j++)
            #pragma unroll
            for (int q = 0; q < 4; q++) acc[i][j][q] = 0.f;

    float4 ra[4], rv[4];
    // stage kt = 0
    {
        #pragma unroll
        for (int i = 0; i < 4; i++)
            ra[i] = *(const float4*)(Ab + (size_t)(i * 32) * 256);
        const int jj = lr;  // 0..31
        const int vrow = (jj < 128) ? (b * SEQ + prevblk * 128 + jj)
                                    : (b * SEQ + w * 128 + jj - 128);
        const float* vp = qkv + (size_t)vrow * QKVN + 4096 + nb + lc;
        #pragma unroll
        for (int i = 0; i < 4; i++) rv[i] = *(const float4*)(vp + i * 32);
    }

    for (int kt = 0; kt < 256; kt += 32) {
        #pragma unroll
        for (int i = 0; i < 4; i++) {
            As[lr + i * 32][lc + 0] = cvt_tf32(ra[i].x);
            As[lr + i * 32][lc + 1] = cvt_tf32(ra[i].y);
            As[lr + i * 32][lc + 2] = cvt_tf32(ra[i].z);
            As[lr + i * 32][lc + 3] = cvt_tf32(ra[i].w);
            Bs[lr][lc + i * 32 + 0] = cvt_tf32(rv[i].x);
            Bs[lr][lc + i * 32 + 1] = cvt_tf32(rv[i].y);
            Bs[lr][lc + i * 32 + 2] = cvt_tf32(rv[i].z);
            Bs[lr][lc + i * 32 + 3] = cvt_tf32(rv[i].w);
        }
        __syncthreads();
        if (kt + 32 < 256) {
            #pragma unroll
            for (int i = 0; i < 4; i++)
                ra[i] = *(const float4*)(Ab + (size_t)(i * 32) * 256 + (kt + 32));
            const int jj = kt + 32 + lr;
            const int vrow = (jj < 128) ? (b * SEQ + prevblk * 128 + jj)
                                        : (b * SEQ + w * 128 + jj - 128);
            const float* vp = qkv + (size_t)vrow * QKVN + 4096 + nb + lc;
            #pragma unroll
            for (int i = 0; i < 4; i++) rv[i] = *(const float4*)(vp + i * 32);
        }
        #pragma unroll
        for (int ks = 0; ks < 4; ks++) {
            const int k0 = ks * 8;
            float a[2][4], bb[8][2];
            #pragma unroll
            for (int mf = 0; mf < 2; mf++) {
                const int r = wm + mf * 16 + g;
                a[mf][0] = As[r][k0 + tg];
                a[mf][1] = As[r + 8][k0 + tg];
                a[mf][2] = As[r][k0 + tg + 4];
                a[mf][3] = As[r + 8][k0 + tg + 4];
            }
            #pragma unroll
            for (int nf = 0; nf < 8; nf++) {
                const int n = wn + nf * 8 + g;
                bb[nf][0] = Bs[k0 + tg][n];
                bb[nf][1] = Bs[k0 + tg + 4][n];
            }
            #pragma unroll
            for (int mf = 0; mf < 2; mf++)
                #pragma unroll
                for (int nf = 0; nf < 8; nf++)
                    mma_tf32(acc[mf][nf][0], acc[mf][nf][1], acc[mf][nf][2], acc[mf][nf][3],
                             a[mf][0], a[mf][1], a[mf][2], a[mf][3],
                             bb[nf][0], bb[nf][1]);
        }
        __syncthreads();
    }

    #pragma unroll
    for (int mf = 0; mf < 2; mf++) {
        #pragma unroll
        for (int nf = 0; nf < 8; nf++) {
            const int row = b * SEQ + w * 128 + wm + mf * 16 + g;
            const int col = nb + wn + nf * 8 + (tg << 1);
            *(float2*)(ao + (size_t)row * DIM + col) =
                make_float2(acc[mf][nf][0], acc[mf][nf][1]);
            *(float2*)(ao + (size_t)(row + 8) * DIM + col) =
                make_float2(acc[mf][nf][2], acc[mf][nf][3]);
        }
    }
}

// ---------------------------------------------------------------------------
// launch
// ---------------------------------------------------------------------------
extern "C" void kernel_launch(void* const* d_in, const int* in_sizes, int n_in,
                              void* d_out, int out_size) {
    const float* x      = (const float*)d_in[0];  // [2, 8192, 2048]
    const float* w_attn = (const float*)d_in[1];  // [6144, 2048]
    const float* w_o    = (const float*)d_in[2];  // [2048, 2048]
    float* out = (float*)d_out;

    float *qkv, *attn, *ao;
    cudaGetSymbolAddress((void**)&qkv, g_qkv);
    cudaGetSymbolAddress((void**)&attn, g_attn);
    cudaGetSymbolAddress((void**)&ao, g_ao);

    dim3 blk(256);
    // qkv = x @ w_attn^T   [16384, 6144]
    gemm_nt_kernel<<<dim3(QKVN / 128, ROWS / 128), blk>>>(x, w_attn, qkv, ROWS, QKVN, DIM);
    // sim -> masked relu^2 attn weights
    attn_sim_kernel<<<dim3(2, NBLK, BATCH), blk>>>(qkv, attn);
    // out_blk = attn @ V2
    attn_pv_kernel<<<dim3(DIM / 128, NBLK, BATCH), blk>>>(qkv, attn, ao);
    // final = ao @ w_o^T
    gemm_nt_kernel<<<dim3(DIM / 128, ROWS / 128), blk>>>(ao, w_o, out, ROWS, DIM, DIM);
}

// round 3
// speedup vs baseline: 1.0380x; 1.0380x over previous
#include <cuda_runtime.h>
#include <cstdint>

// Problem constants: B=2, T=8192, D=2048, W=128
#define BATCH 2
#define SEQ   8192
#define DIM   2048
#define WIN   128
#define NBLK  64
#define ROWS  16384
#define QKVN  6144

// Scratch (device globals: the sanctioned alloc-free workaround)
__device__ float g_qkv[(size_t)ROWS * QKVN];
__device__ float g_attn[(size_t)BATCH * NBLK * 128 * 256];
__device__ float g_ao[(size_t)ROWS * DIM];

// ---------------------------------------------------------------------------
// helpers
// ---------------------------------------------------------------------------
__device__ __forceinline__ uint32_t smem_u32(const void* p) {
    uint32_t a;
    asm("{ .reg .u64 t; cvta.to.shared.u64 t, %1; cvt.u32.u64 %0, t; }" : "=r"(a) : "l"(p));
    return a;
}
__device__ __forceinline__ float cvt_tf32(float x) {
    uint32_t u;
    asm("cvt.rna.tf32.f32 %0, %1;" : "=r"(u) : "f"(x));
    return __uint_as_float(u);
}

// mma with b32 fragment registers (from ldmatrix)
__device__ __forceinline__ void mma_tf32u(float& d0, float& d1, float& d2, float& d3,
                                          uint32_t a0, uint32_t a1, uint32_t a2, uint32_t a3,
                                          uint32_t b0, uint32_t b1) {
    asm volatile(
        "mma.sync.aligned.m16n8k8.row.col.f32.tf32.tf32.f32 "
        "{%0,%1,%2,%3}, {%4,%5,%6,%7}, {%8,%9}, {%0,%1,%2,%3};\n"
        : "+f"(d0), "+f"(d1), "+f"(d2), "+f"(d3)
        : "r"(a0), "r"(a1), "r"(a2), "r"(a3), "r"(b0), "r"(b1));
}
__device__ __forceinline__ void mma_tf32(float& d0, float& d1, float& d2, float& d3,
                                         float a0, float a1, float a2, float a3,
                                         float b0, float b1) {
    mma_tf32u(d0, d1, d2, d3,
              __float_as_uint(a0), __float_as_uint(a1),
              __float_as_uint(a2), __float_as_uint(a3),
              __float_as_uint(b0), __float_as_uint(b1));
}

#define LDSM_X4(r0, r1, r2, r3, addr)                                          \
    asm volatile("ldmatrix.sync.aligned.m8n8.x4.shared.b16 {%0,%1,%2,%3}, [%4];" \
                 : "=r"(r0), "=r"(r1), "=r"(r2), "=r"(r3) : "r"(addr))

// ---------------------------------------------------------------------------
// Generic NT GEMM: C[M,N] = A[M,K] @ B[N,K]^T  (row-major, K contiguous)
// CTA tile 128x128, K-tile 32, 256 threads (8 warps: 4 M x 2 N).
// Fragment loads via ldmatrix.x4 on b32 data (CUTLASS tf32 trick), with
// fragment double-buffering across the 4 k8-steps of each K-tile.
// ---------------------------------------------------------------------------
__global__ __launch_bounds__(256, 1)
void gemm_nt_kernel(const float* __restrict__ A, const float* __restrict__ B,
                    float* __restrict__ C, int M, int N, int K) {
    __shared__ float As[128][36];   // row stride 144B: LDSM rows hit distinct sub-banks
    __shared__ float Bs[128][36];

    const int tid  = threadIdx.x;
    const int warp = tid >> 5, lane = tid & 31;
    const int wm = (warp & 3) << 5;   // 0,32,64,96
    const int wn = (warp >> 2) << 6;  // 0,64
    const int g  = lane >> 2, tg = lane & 3;
    const int lr = tid >> 3;          // staging row 0..31
    const int lc = (tid & 7) << 2;    // staging col 0..28 step 4

    // ldmatrix lane-address precompute
    const int sel = lane >> 3;        // which of the 4 m8n8 matrices this lane feeds
    const int i8  = lane & 7;
    const uint32_t smA = smem_u32(&As[0][0]);
    const uint32_t smB = smem_u32(&Bs[0][0]);
    uint32_t a_addr[2], b_addr[4];
    #pragma unroll
    for (int mf = 0; mf < 2; mf++) {
        const int row = wm + 16 * mf + (sel & 1) * 8 + i8;     // a0/a1 row split
        a_addr[mf] = smA + (uint32_t)(row * 36 + (sel >> 1) * 4) * 4;  // a2/a3 k+4
    }
    #pragma unroll
    for (int np = 0; np < 4; np++) {
        const int row = wn + 8 * (2 * np + (sel >> 1)) + i8;   // nf pair
        b_addr[np] = smB + (uint32_t)(row * 36) * 4 + (sel & 1) * 16;  // b1 k+4
    }

    const float* Ab = A + (size_t)(blockIdx.y * 128 + lr) * K + lc;
    const float* Bb = B + (size_t)(blockIdx.x * 128 + lr) * K + lc;

    float acc[2][8][4];
    #pragma unroll
    for (int i = 0; i < 2; i++)
        #pragma unroll
        for (int j = 0; j < 8; j++)
            #pragma unroll
            for (int q = 0; q < 4; q++) acc[i][j][q] = 0.f;

    float4 ra[4], rb[4];
    #pragma unroll
    for (int i = 0; i < 4; i++) {
        ra[i] = *(const float4*)(Ab + (size_t)(i * 32) * K);
        rb[i] = *(const float4*)(Bb + (size_t)(i * 32) * K);
    }

    uint32_t af[2][2][4];   // [buf][mf][a0..a3]
    uint32_t bf[2][4][4];   // [buf][np][b0(e),b1(e),b0(o),b1(o)]

    for (int kt = 0; kt < K; kt += 32) {
        #pragma unroll
        for (int i = 0; i < 4; i++) {
            As[lr + i * 32][lc + 0] = cvt_tf32(ra[i].x);
            As[lr + i * 32][lc + 1] = cvt_tf32(ra[i].y);
            As[lr + i * 32][lc + 2] = cvt_tf32(ra[i].z);
            As[lr + i * 32][lc + 3] = cvt_tf32(ra[i].w);
            Bs[lr + i * 32][lc + 0] = cvt_tf32(rb[i].x);
            Bs[lr + i * 32][lc + 1] = cvt_tf32(rb[i].y);
            Bs[lr + i * 32][lc + 2] = cvt_tf32(rb[i].z);
            Bs[lr + i * 32][lc + 3] = cvt_tf32(rb[i].w);
        }
        __syncthreads();
        if (kt + 32 < K) {   // gmem prefetch rides under the MMA section
            #pragma unroll
            for (int i = 0; i < 4; i++) {
                ra[i] = *(const float4*)(Ab + (size_t)(i * 32) * K + (kt + 32));
                rb[i] = *(const float4*)(Bb + (size_t)(i * 32) * K + (kt + 32));
            }
        }
        // fragment pipeline over 4 k8-steps
        #pragma unroll
        for (int mf = 0; mf < 2; mf++)
            LDSM_X4(af[0][mf][0], af[0][mf][1], af[0][mf][2], af[0][mf][3], a_addr[mf]);
        #pragma unroll
        for (int np = 0; np < 4; np++)
            LDSM_X4(bf[0][np][0], bf[0][np][1], bf[0][np][2], bf[0][np][3], b_addr[np]);
        #pragma unroll
        for (int ks = 0; ks < 4; ks++) {
            const int cur = ks & 1, nxt = cur ^ 1;
            if (ks < 3) {
                const uint32_t ko = (uint32_t)(ks + 1) * 32;  // 8 floats
                #pragma unroll
                for (int mf = 0; mf < 2; mf++)
                    LDSM_X4(af[nxt][mf][0], af[nxt][mf][1], af[nxt][mf][2], af[nxt][mf][3],
                            a_addr[mf] + ko);
                #pragma unroll
                for (int np = 0; np < 4; np++)
                    LDSM_X4(bf[nxt][np][0], bf[nxt][np][1], bf[nxt][np][2], bf[nxt][np][3],
                            b_addr[np] + ko);
            }
            #pragma unroll
            for (int mf = 0; mf < 2; mf++)
                #pragma unroll
                for (int np = 0; np < 4; np++) {
                    mma_tf32u(acc[mf][2 * np + 0][0], acc[mf][2 * np + 0][1],
                              acc[mf][2 * np + 0][2], acc[mf][2 * np + 0][3],
                              af[cur][mf][0], af[cur][mf][1], af[cur][mf][2], af[cur][mf][3],
                              bf[cur][np][0], bf[cur][np][1]);
                    mma_tf32u(acc[mf][2 * np + 1][0], acc[mf][2 * np + 1][1],
                              acc[mf][2 * np + 1][2], acc[mf][2 * np + 1][3],
                              af[cur][mf][0], af[cur][mf][1], af[cur][mf][2], af[cur][mf][3],
                              bf[cur][np][2], bf[cur][np][3]);
                }
        }
        __syncthreads();
    }

    #pragma unroll
    for (int mf = 0; mf < 2; mf++) {
        #pragma unroll
        for (int nf = 0; nf < 8; nf++) {
            const int row = blockIdx.y * 128 + wm + mf * 16 + g;
            const int col = blockIdx.x * 128 + wn + nf * 8 + (tg << 1);
            *(float2*)(C + (size_t)row * N + col) =
                make_float2(acc[mf][nf][0], acc[mf][nf][1]);
            *(float2*)(C + (size_t)(row + 8) * N + col) =
                make_float2(acc[mf][nf][2], acc[mf][nf][3]);
        }
    }
}

// ---------------------------------------------------------------------------
// sim kernel: per (b,w,half) 128x128 QK^T over K=2048, mask + 1/W + relu^2.
// Same ldmatrix fragment pipeline as gemm_nt.
// ---------------------------------------------------------------------------
__global__ __launch_bounds__(256, 1)
void attn_sim_kernel(const float* __restrict__ qkv, float* __restrict__ attnOut) {
    const int half = blockIdx.x, w = blockIdx.y, b = blockIdx.z;
    __shared__ float As[128][36];
    __shared__ float Bs[128][36];

    const int tid  = threadIdx.x;
    const int warp = tid >> 5, lane = tid & 31;
    const int wm = (warp & 3) << 5;
    const int wn = (warp >> 2) << 6;
    const int g  = lane >> 2, tg = lane & 3;
    const int lr = tid >> 3;
    const int lc = (tid & 7) << 2;

    const int sel = lane >> 3;
    const int i8  = lane & 7;
    const uint32_t smA = smem_u32(&As[0][0]);
    const uint32_t smB = smem_u32(&Bs[0][0]);
    uint32_t a_addr[2], b_addr[4];
    #pragma unroll
    for (int mf = 0; mf < 2; mf++) {
        const int row = wm + 16 * mf + (sel & 1) * 8 + i8;
        a_addr[mf] = smA + (uint32_t)(row * 36 + (sel >> 1) * 4) * 4;
    }
    #pragma unroll
    for (int np = 0; np < 4; np++) {
        const int row = wn + 8 * (2 * np + (sel >> 1)) + i8;
        b_addr[np] = smB + (uint32_t)(row * 36) * 4 + (sel & 1) * 16;
    }

    const int kblk = (half == 0) ? (w > 0 ? w - 1 : 0) : w;
    const float* Ab = qkv + (size_t)(b * SEQ + w * 128 + lr) * QKVN + lc;
    const float* Bb = qkv + (size_t)(b * SEQ + kblk * 128 + lr) * QKVN + 2048 + lc;

    float acc[2][8][4];
    #pragma unroll
    for (int i = 0; i < 2; i++)
        #pragma unroll
        for (int j = 0; j < 8; j++)
            #pragma unroll
            for (int q = 0; q < 4; q++) acc[i][j][q] = 0.f;

    float4 ra[4], rb[4];
    #pragma unroll
    for (int i = 0; i < 4; i++) {
        ra[i] = *(const float4*)(Ab + (size_t)(i * 32) * QKVN);
        rb[i] = *(const float4*)(Bb + (size_t)(i * 32) * QKVN);
    }

    uint32_t af[2][2][4];
    uint32_t bf[2][4][4];

    for (int kt = 0; kt < DIM; kt += 32) {
        #pragma unroll
        for (int i = 0; i < 4; i++) {
            As[lr + i * 32][lc + 0] = cvt_tf32(ra[i].x);
            As[lr + i * 32][lc + 1] = cvt_tf32(ra[i].y);
            As[lr + i * 32][lc + 2] = cvt_tf32(ra[i].z);
            As[lr + i * 32][lc + 3] = cvt_tf32(ra[i].w);
            Bs[lr + i * 32][lc + 0] = cvt_tf32(rb[i].x);
            Bs[lr + i * 32][lc + 1] = cvt_tf32(rb[i].y);
            Bs[lr + i * 32][lc + 2] = cvt_tf32(rb[i].z);
            Bs[lr + i * 32][lc + 3] = cvt_tf32(rb[i].w);
        }
        __syncthreads();
        if (kt + 32 < DIM) {
            #pragma unroll
            for (int i = 0; i < 4; i++) {
                ra[i] = *(const float4*)(Ab + (size_t)(i * 32) * QKVN + (kt + 32));
                rb[i] = *(const float4*)(Bb + (size_t)(i * 32) * QKVN + (kt + 32));
            }
        }
        #pragma unroll
        for (int mf = 0; mf < 2; mf++)
            LDSM_X4(af[0][mf][0], af[0][mf][1], af[0][mf][2], af[0][mf][3], a_addr[mf]);
        #pragma unroll
        for (int np = 0; np < 4; np++)
            LDSM_X4(bf[0][np][0], bf[0][np][1], bf[0][np][2], bf[0][np][3], b_addr[np]);
        #pragma unroll
        for (int ks = 0; ks < 4; ks++) {
            const int cur = ks & 1, nxt = cur ^ 1;
            if (ks < 3) {
                const uint32_t ko = (uint32_t)(ks + 1) * 32;
                #pragma unroll
                for (int mf = 0; mf < 2; mf++)
                    LDSM_X4(af[nxt][mf][0], af[nxt][mf][1], af[nxt][mf][2], af[nxt][mf][3],
                            a_addr[mf] + ko);
                #pragma unroll
                for (int np = 0; np < 4; np++)
                    LDSM_X4(bf[nxt][np][0], bf[nxt][np][1], bf[nxt][np][2], bf[nxt][np][3],
                            b_addr[np] + ko);
            }
            #pragma unroll
            for (int mf = 0; mf < 2; mf++)
                #pragma unroll
                for (int np = 0; np < 4; np++) {
                    mma_tf32u(acc[mf][2 * np + 0][0], acc[mf][2 * np + 0][1],
                              acc[mf][2 * np + 0][2], acc[mf][2 * np + 0][3],
                              af[cur][mf][0], af[cur][mf][1], af[cur][mf][2], af[cur][mf][3],
                              bf[cur][np][0], bf[cur][np][1]);
                    mma_tf32u(acc[mf][2 * np + 1][0], acc[mf][2 * np + 1][1],
                              acc[mf][2 * np + 1][2], acc[mf][2 * np + 1][3],
                              af[cur][mf][0], af[cur][mf][1], af[cur][mf][2], af[cur][mf][3],
                              bf[cur][np][2], bf[cur][np][3]);
                }
        }
        __syncthreads();
    }

    const bool halfvalid = (half == 1) || (w > 0);
    const float inv_w = 1.0f / (float)WIN;
    float* Cb = attnOut + ((size_t)(b * NBLK + w) * 128) * 256 + half * 128;

    #pragma unroll
    for (int mf = 0; mf < 2; mf++) {
        #pragma unroll
        for (int nf = 0; nf < 8; nf++) {
            const int qi0 = wm + mf * 16 + g;
            const int kj  = wn + nf * 8 + (tg << 1);
            #pragma unroll
            for (int rr = 0; rr < 2; rr++) {
                const int qi = qi0 + rr * 8;
                float2 v;
                float s0 = acc[mf][nf][rr * 2 + 0] * inv_w;
                float s1 = acc[mf][nf][rr * 2 + 1] * inv_w;
                bool k0 = halfvalid && ((half == 0) ? (qi <= kj)     : (qi >= kj));
                bool k1 = halfvalid && ((half == 0) ? (qi <= kj + 1) : (qi >= kj + 1));
                float r0 = k0 ? fmaxf(s0, 0.f) : 0.f;
                float r1 = k1 ? fmaxf(s1, 0.f) : 0.f;
                v.x = r0 * r0;
                v.y = r1 * r1;
                *(float2*)(Cb + (size_t)qi * 256 + kj) = v;
            }
        }
    }
}

// ---------------------------------------------------------------------------
// PV kernel: out_blk = attn[128,256] @ V2[256, ntile 128 cols]
// (k-major B in SMEM; scalar fragment loads — small fraction of runtime)
// ---------------------------------------------------------------------------
__global__ __launch_bounds__(256, 1)
void attn_pv_kernel(const float* __restrict__ qkv, const float* __restrict__ attn,
                    float* __restrict__ ao) {
    const int nb = blockIdx.x * 128, w = blockIdx.y, b = blockIdx.z;
    __shared__ float As[128][36];
    __shared__ float Bs[32][136];

    const int tid  = threadIdx.x;
    const int warp = tid >> 5, lane = tid & 31;
    const int wm = (warp & 3) << 5;
    const int wn = (warp >> 2) << 6;
    const int g  = lane >> 2, tg = lane & 3;
    const int lr = tid >> 3;
    const int lc = (tid & 7) << 2;

    const int prevblk = (w > 0) ? w - 1 : 0;
    const float* Ab = attn + ((size_t)(b * NBLK + w) * 128 + lr) * 256 + lc;

    float acc[2][8][4];
    #pragma unroll
    for (int i = 0; i < 2; i++)
        #pragma unroll
        for (int j = 0; j < 8; j++)
            #pragma unroll
            for (int q = 0; q < 4; q++) acc[i][j][q] = 0.f;

    float4 ra[4], rv[4];
    {
        #pragma unroll
        for (int i = 0; i < 4; i++)
            ra[i] = *(const float4*)(Ab + (size_t)(i * 32) * 256);
        const int jj = lr;
        const int vrow = (jj < 128) ? (b * SEQ + prevblk * 128 + jj)
                                    : (b * SEQ + w * 128 + jj - 128);
        const float* vp = qkv + (size_t)vrow * QKVN + 4096 + nb + lc;
        #pragma unroll
        for (int i = 0; i < 4; i++) rv[i] = *(const float4*)(vp + i * 32);
    }

    for (int kt = 0; kt < 256; kt += 32) {
        #pragma unroll
        for (int i = 0; i < 4; i++) {
            As[lr + i * 32][lc + 0] = cvt_tf32(ra[i].x);
            As[lr + i * 32][lc + 1] = cvt_tf32(ra[i].y);
            As[lr + i * 32][lc + 2] = cvt_tf32(ra[i].z);
            As[lr + i * 32][lc + 3] = cvt_tf32(ra[i].w);
            Bs[lr][lc + i * 32 + 0] = cvt_tf32(rv[i].x);
            Bs[lr][lc + i * 32 + 1] = cvt_tf32(rv[i].y);
            Bs[lr][lc + i * 32 + 2] = cvt_tf32(rv[i].z);
            Bs[lr][lc + i * 32 + 3] = cvt_tf32(rv[i].w);
        }
        __syncthreads();
        if (kt + 32 < 256) {
            #pragma unroll
            for (int i = 0; i < 4; i++)
                ra[i] = *(const float4*)(Ab + (size_t)(i * 32) * 256 + (kt + 32));
            const int jj = kt + 32 + lr;
            const int vrow = (jj < 128) ? (b * SEQ + prevblk * 128 + jj)
                                        : (b * SEQ + w * 128 + jj - 128);
            const float* vp = qkv + (size_t)vrow * QKVN + 4096 + nb + lc;
            #pragma unroll
            for (int i = 0; i < 4; i++) rv[i] = *(const float4*)(vp + i * 32);
        }
        #pragma unroll
        for (int ks = 0; ks < 4; ks++) {
            const int k0 = ks * 8;
            float a[2][4], bb[8][2];
            #pragma unroll
            for (int mf = 0; mf < 2; mf++) {
                const int r = wm + mf * 16 + g;
                a[mf][0] = As[r][k0 + tg];
                a[mf][1] = As[r + 8][k0 + tg];
                a[mf][2] = As[r][k0 + tg + 4];
                a[mf][3] = As[r + 8][k0 + tg + 4];
            }
            #pragma unroll
            for (int nf = 0; nf < 8; nf++) {
                const int n = wn + nf * 8 + g;
                bb[nf][0] = Bs[k0 + tg][n];
                bb[nf][1] = Bs[k0 + tg + 4][n];
            }
            #pragma unroll
            for (int mf = 0; mf < 2; mf++)
                #pragma unroll
                for (int nf = 0; nf < 8; nf++)
                    mma_tf32(acc[mf][nf][0], acc[mf][nf][1], acc[mf][nf][2], acc[mf][nf][3],
                             a[mf][0], a[mf][1], a[mf][2], a[mf][3],
                             bb[nf][0], bb[nf][1]);
        }
        __syncthreads();
    }

    #pragma unroll
    for (int mf = 0; mf < 2; mf++) {
        #pragma unroll
        for (int nf = 0; nf < 8; nf++) {
            const int row = b * SEQ + w * 128 + wm + mf * 16 + g;
            const int col = nb + wn + nf * 8 + (tg << 1);
            *(float2*)(ao + (size_t)row * DIM + col) =
                make_float2(acc[mf][nf][0], acc[mf][nf][1]);
            *(float2*)(ao + (size_t)(row + 8) * DIM + col) =
                make_float2(acc[mf][nf][2], acc[mf][nf][3]);
        }
    }
}

// ---------------------------------------------------------------------------
// launch
// ---------------------------------------------------------------------------
extern "C" void kernel_launch(void* const* d_in, const int* in_sizes, int n_in,
                              void* d_out, int out_size) {
    const float* x      = (const float*)d_in[0];  // [2, 8192, 2048]
    const float* w_attn = (const float*)d_in[1];  // [6144, 2048]
    const float* w_o    = (const float*)d_in[2];  // [2048, 2048]
    float* out = (float*)d_out;

    float *qkv, *attn, *ao;
    cudaGetSymbolAddress((void**)&qkv, g_qkv);
    cudaGetSymbolAddress((void**)&attn, g_attn);
    cudaGetSymbolAddress((void**)&ao, g_ao);

    dim3 blk(256);
    // qkv = x @ w_attn^T   [16384, 6144]
    gemm_nt_kernel<<<dim3(QKVN / 128, ROWS / 128), blk>>>(x, w_attn, qkv, ROWS, QKVN, DIM);
    // sim -> masked relu^2 attn weights
    attn_sim_kernel<<<dim3(2, NBLK, BATCH), blk>>>(qkv, attn);
    // out_blk = attn @ V2
    attn_pv_kernel<<<dim3(DIM / 128, NBLK, BATCH), blk>>>(qkv, attn, ao);
    // final = ao @ w_o^T
    gemm_nt_kernel<<<dim3(DIM / 128, ROWS / 128), blk>>>(ao, w_o, out, ROWS, DIM, DIM);
}

// round 4
// speedup vs baseline: 1.4569x; 1.4036x over previous
#include <cuda_runtime.h>
#include <cstdint>

// Problem constants: B=2, T=8192, D=2048, W=128
#define BATCH 2
#define SEQ   8192
#define DIM   2048
#define WIN   128
#define NBLK  64
#define ROWS  16384
#define QKVN  6144

// Scratch (device globals: the sanctioned alloc-free workaround)
__device__ float g_qkv[(size_t)ROWS * QKVN];                 // rounded tf32 values
__device__ float g_attn[(size_t)BATCH * NBLK * 128 * 256];   // rounded tf32 values
__device__ float g_ao[(size_t)ROWS * DIM];                   // rounded tf32 values
__device__ float g_xr[(size_t)ROWS * DIM];                   // rounded x
__device__ float g_war[(size_t)QKVN * DIM];                  // rounded w_attn
__device__ float g_wor[(size_t)DIM * DIM];                   // rounded w_o

// ---------------------------------------------------------------------------
// helpers
// ---------------------------------------------------------------------------
__device__ __forceinline__ uint32_t smem_u32(const void* p) {
    uint32_t a;
    asm("{ .reg .u64 t; cvta.to.shared.u64 t, %1; cvt.u32.u64 %0, t; }" : "=r"(a) : "l"(p));
    return a;
}
__device__ __forceinline__ float cvt_tf32(float x) {
    uint32_t u;
    asm("cvt.rna.tf32.f32 %0, %1;" : "=r"(u) : "f"(x));
    return __uint_as_float(u);
}

__device__ __forceinline__ void mma_tf32u(float& d0, float& d1, float& d2, float& d3,
                                          uint32_t a0, uint32_t a1, uint32_t a2, uint32_t a3,
                                          uint32_t b0, uint32_t b1) {
    asm volatile(
        "mma.sync.aligned.m16n8k8.row.col.f32.tf32.tf32.f32 "
        "{%0,%1,%2,%3}, {%4,%5,%6,%7}, {%8,%9}, {%0,%1,%2,%3};\n"
        : "+f"(d0), "+f"(d1), "+f"(d2), "+f"(d3)
        : "r"(a0), "r"(a1), "r"(a2), "r"(a3), "r"(b0), "r"(b1));
}
__device__ __forceinline__ void mma_tf32(float& d0, float& d1, float& d2, float& d3,
                                         float a0, float a1, float a2, float a3,
                                         float b0, float b1) {
    mma_tf32u(d0, d1, d2, d3,
              __float_as_uint(a0), __float_as_uint(a1),
              __float_as_uint(a2), __float_as_uint(a3),
              __float_as_uint(b0), __float_as_uint(b1));
}

#define LDSM_X4(r0, r1, r2, r3, addr)                                          \
    asm volatile("ldmatrix.sync.aligned.m8n8.x4.shared.b16 {%0,%1,%2,%3}, [%4];" \
                 : "=r"(r0), "=r"(r1), "=r"(r2), "=r"(r3) : "r"(addr))

#define CP_ASYNC16(dst, src)                                                   \
    asm volatile("cp.async.cg.shared.global [%0], [%1], 16;"                   \
                 :: "r"(dst), "l"(src) : "memory")
#define CP_COMMIT() asm volatile("cp.async.commit_group;" ::: "memory")
#define CP_WAIT1()  asm volatile("cp.async.wait_group 1;" ::: "memory")
#define CP_WAIT0()  asm volatile("cp.async.wait_group 0;" ::: "memory")

// Per-stage SMEM geometry (floats): 128 rows x 36 cols (+4 pad, LDSM conflict-free)
#define STG_B   18432                   // bytes per matrix per stage
#define B_BASE  36864                   // Bs base byte offset (after 2 A stages)
#define GEMM_SMEM 73728                 // 2 stages x (A + B)

// ---------------------------------------------------------------------------
// NT GEMM: C[M,N] = A[M,K] @ B[N,K]^T. Inputs pre-rounded to tf32 values.
// cp.async 2-stage pipeline, 128x128 CTA tile, 256 threads, 2 CTAs/SM.
// A rows stride lda, B rows stride ldb (both K-contiguous).
// ---------------------------------------------------------------------------
__global__ __launch_bounds__(256, 2)
void gemm_nt_kernel(const float* __restrict__ A, const float* __restrict__ B,
                    float* __restrict__ C, int lda, int ldb, int N, int K,
                    int round_out) {
    extern __shared__ __align__(128) float smem[];
    const uint32_t smem_base = smem_u32(smem);

    const int tid  = threadIdx.x;
    const int warp = tid >> 5, lane = tid & 31;
    const int wm = (warp & 3) << 5;
    const int wn = (warp >> 2) << 6;
    const int g  = lane >> 2, tg = lane & 3;
    const int lr = tid >> 3;          // copy row 0..31
    const int c4 = tid & 7;           // copy 16B-chunk 0..7

    // ldmatrix lane addresses (stage 0 bases)
    const int sel = lane >> 3;
    const int i8  = lane & 7;
    uint32_t a_addr[2], b_addr[4];
    #pragma unroll
    for (int mf = 0; mf < 2; mf++) {
        const int row = wm + 16 * mf + (sel & 1) * 8 + i8;
        a_addr[mf] = smem_base + (uint32_t)(row * 36 + (sel >> 1) * 4) * 4;
    }
    #pragma unroll
    for (int np = 0; np < 4; np++) {
        const int row = wn + 8 * (2 * np + (sel >> 1)) + i8;
        b_addr[np] = smem_base + B_BASE + (uint32_t)(row * 36) * 4 + (sel & 1) * 16;
    }

    const float* Ab = A + (size_t)(blockIdx.y * 128 + lr) * lda + c4 * 4;
    const float* Bb = B + (size_t)(blockIdx.x * 128 + lr) * ldb + c4 * 4;
    const uint32_t dA = smem_base + (uint32_t)(lr * 36 + c4 * 4) * 4;
    const uint32_t dB = smem_base + B_BASE + (uint32_t)(lr * 36 + c4 * 4) * 4;

    float acc[2][8][4];
    #pragma unroll
    for (int i = 0; i < 2; i++)
        #pragma unroll
        for (int j = 0; j < 8; j++)
            #pragma unroll
            for (int q = 0; q < 4; q++) acc[i][j][q] = 0.f;

    // prologue: stage 0
    #pragma unroll
    for (int j = 0; j < 4; j++) {
        CP_ASYNC16(dA + j * (32 * 144), Ab + (size_t)(j * 32) * lda);
        CP_ASYNC16(dB + j * (32 * 144), Bb + (size_t)(j * 32) * ldb);
    }
    CP_COMMIT();

    const int NT = K >> 5;
    uint32_t af[2][4], bf[4][4];

    for (int it = 0; it < NT; it++) {
        const int s = it & 1;
        if (it + 1 < NT) {
            const uint32_t o = (s ^ 1) * STG_B;
            const float* An = Ab + (it + 1) * 32;
            const float* Bn = Bb + (it + 1) * 32;
            #pragma unroll
            for (int j = 0; j < 4; j++) {
                CP_ASYNC16(dA + o + j * (32 * 144), An + (size_t)(j * 32) * lda);
                CP_ASYNC16(dB + o + j * (32 * 144), Bn + (size_t)(j * 32) * ldb);
            }
            CP_COMMIT();
            CP_WAIT1();
        } else {
            CP_WAIT0();
        }
        __syncthreads();

        const uint32_t so = s * STG_B;
        #pragma unroll
        for (int ks = 0; ks < 4; ks++) {
            const uint32_t ko = so + (uint32_t)ks * 32;
            #pragma unroll
            for (int mf = 0; mf < 2; mf++)
                LDSM_X4(af[mf][0], af[mf][1], af[mf][2], af[mf][3], a_addr[mf] + ko);
            #pragma unroll
            for (int np = 0; np < 4; np++)
                LDSM_X4(bf[np][0], bf[np][1], bf[np][2], bf[np][3], b_addr[np] + ko);
            #pragma unroll
            for (int mf = 0; mf < 2; mf++)
                #pragma unroll
                for (int np = 0; np < 4; np++) {
                    mma_tf32u(acc[mf][2 * np + 0][0], acc[mf][2 * np + 0][1],
                              acc[mf][2 * np + 0][2], acc[mf][2 * np + 0][3],
                              af[mf][0], af[mf][1], af[mf][2], af[mf][3],
                              bf[np][0], bf[np][1]);
                    mma_tf32u(acc[mf][2 * np + 1][0], acc[mf][2 * np + 1][1],
                              acc[mf][2 * np + 1][2], acc[mf][2 * np + 1][3],
                              af[mf][0], af[mf][1], af[mf][2], af[mf][3],
                              bf[np][2], bf[np][3]);
                }
        }
        __syncthreads();
    }

    #pragma unroll
    for (int mf = 0; mf < 2; mf++) {
        #pragma unroll
        for (int nf = 0; nf < 8; nf++) {
            const int row = blockIdx.y * 128 + wm + mf * 16 + g;
            const int col = blockIdx.x * 128 + wn + nf * 8 + (tg << 1);
            float2 v0 = make_float2(acc[mf][nf][0], acc[mf][nf][1]);
            float2 v1 = make_float2(acc[mf][nf][2], acc[mf][nf][3]);
            if (round_out) {
                v0.x = cvt_tf32(v0.x); v0.y = cvt_tf32(v0.y);
                v1.x = cvt_tf32(v1.x); v1.y = cvt_tf32(v1.y);
            }
            *(float2*)(C + (size_t)row * N + col) = v0;
            *(float2*)(C + (size_t)(row + 8) * N + col) = v1;
        }
    }
}

// ---------------------------------------------------------------------------
// sim kernel: per (b,w,half) 128x128 QK^T over K=2048, mask + 1/W + relu^2.
// Same cp.async pipeline; inputs (qkv) pre-rounded.
// ---------------------------------------------------------------------------
__global__ __launch_bounds__(256, 2)
void attn_sim_kernel(const float* __restrict__ qkv, float* __restrict__ attnOut) {
    extern __shared__ __align__(128) float smem[];
    const uint32_t smem_base = smem_u32(smem);
    const int half = blockIdx.x, w = blockIdx.y, b = blockIdx.z;

    const int tid  = threadIdx.x;
    const int warp = tid >> 5, lane = tid & 31;
    const int wm = (warp & 3) << 5;
    const int wn = (warp >> 2) << 6;
    const int g  = lane >> 2, tg = lane & 3;
    const int lr = tid >> 3;
    const int c4 = tid & 7;

    const int sel = lane >> 3;
    const int i8  = lane & 7;
    uint32_t a_addr[2], b_addr[4];
    #pragma unroll
    for (int mf = 0; mf < 2; mf++) {
        const int row = wm + 16 * mf + (sel & 1) * 8 + i8;
        a_addr[mf] = smem_base + (uint32_t)(row * 36 + (sel >> 1) * 4) * 4;
    }
    #pragma unroll
    for (int np = 0; np < 4; np++) {
        const int row = wn + 8 * (2 * np + (sel >> 1)) + i8;
        b_addr[np] = smem_base + B_BASE + (uint32_t)(row * 36) * 4 + (sel & 1) * 16;
    }

    const int kblk = (half == 0) ? (w > 0 ? w - 1 : 0) : w;
    const float* Ab = qkv + (size_t)(b * SEQ + w * 128 + lr) * QKVN + c4 * 4;
    const float* Bb = qkv + (size_t)(b * SEQ + kblk * 128 + lr) * QKVN + 2048 + c4 * 4;
    const uint32_t dA = smem_base + (uint32_t)(lr * 36 + c4 * 4) * 4;
    const uint32_t dB = smem_base + B_BASE + (uint32_t)(lr * 36 + c4 * 4) * 4;

    float acc[2][8][4];
    #pragma unroll
    for (int i = 0; i < 2; i++)
        #pragma unroll
        for (int j = 0; j < 8; j++)
            #pragma unroll
            for (int q = 0; q < 4; q++) acc[i][j][q] = 0.f;

    #pragma unroll
    for (int j = 0; j < 4; j++) {
        CP_ASYNC16(dA + j * (32 * 144), Ab + (size_t)(j * 32) * QKVN);
        CP_ASYNC16(dB + j * (32 * 144), Bb + (size_t)(j * 32) * QKVN);
    }
    CP_COMMIT();

    const int NT = DIM >> 5;
    uint32_t af[2][4], bf[4][4];

    for (int it = 0; it < NT; it++) {
        const int s = it & 1;
        if (it + 1 < NT) {
            const uint32_t o = (s ^ 1) * STG_B;
            const float* An = Ab + (it + 1) * 32;
            const float* Bn = Bb + (it + 1) * 32;
            #pragma unroll
            for (int j = 0; j < 4; j++) {
                CP_ASYNC16(dA + o + j * (32 * 144), An + (size_t)(j * 32) * QKVN);
                CP_ASYNC16(dB + o + j * (32 * 144), Bn + (size_t)(j * 32) * QKVN);
            }
            CP_COMMIT();
            CP_WAIT1();
        } else {
            CP_WAIT0();
        }
        __syncthreads();

        const uint32_t so = s * STG_B;
        #pragma unroll
        for (int ks = 0; ks < 4; ks++) {
            const uint32_t ko = so + (uint32_t)ks * 32;
            #pragma unroll
            for (int mf = 0; mf < 2; mf++)
                LDSM_X4(af[mf][0], af[mf][1], af[mf][2], af[mf][3], a_addr[mf] + ko);
            #pragma unroll
            for (int np = 0; np < 4; np++)
                LDSM_X4(bf[np][0], bf[np][1], bf[np][2], bf[np][3], b_addr[np] + ko);
            #pragma unroll
            for (int mf = 0; mf < 2; mf++)
                #pragma unroll
                for (int np = 0; np < 4; np++) {
                    mma_tf32u(acc[mf][2 * np + 0][0], acc[mf][2 * np + 0][1],
                              acc[mf][2 * np + 0][2], acc[mf][2 * np + 0][3],
                              af[mf][0], af[mf][1], af[mf][2], af[mf][3],
                              bf[np][0], bf[np][1]);
                    mma_tf32u(acc[mf][2 * np + 1][0], acc[mf][2 * np + 1][1],
                              acc[mf][2 * np + 1][2], acc[mf][2 * np + 1][3],
                              af[mf][0], af[mf][1], af[mf][2], af[mf][3],
                              bf[np][2], bf[np][3]);
                }
        }
        __syncthreads();
    }

    const bool halfvalid = (half == 1) || (w > 0);
    const float inv_w = 1.0f / (float)WIN;
    float* Cb = attnOut + ((size_t)(b * NBLK + w) * 128) * 256 + half * 128;

    #pragma unroll
    for (int mf = 0; mf < 2; mf++) {
        #pragma unroll
        for (int nf = 0; nf < 8; nf++) {
            const int qi0 = wm + mf * 16 + g;
            const int kj  = wn + nf * 8 + (tg << 1);
            #pragma unroll
            for (int rr = 0; rr < 2; rr++) {
                const int qi = qi0 + rr * 8;
                float s0 = acc[mf][nf][rr * 2 + 0] * inv_w;
                float s1 = acc[mf][nf][rr * 2 + 1] * inv_w;
                bool k0 = halfvalid && ((half == 0) ? (qi <= kj)     : (qi >= kj));
                bool k1 = halfvalid && ((half == 0) ? (qi <= kj + 1) : (qi >= kj + 1));
                float r0 = k0 ? fmaxf(s0, 0.f) : 0.f;
                float r1 = k1 ? fmaxf(s1, 0.f) : 0.f;
                float2 v;
                v.x = cvt_tf32(r0 * r0);   // pre-rounded for PV's cp-free path
                v.y = cvt_tf32(r1 * r1);
                *(float2*)(Cb + (size_t)qi * 256 + kj) = v;
            }
        }
    }
}

// ---------------------------------------------------------------------------
// PV kernel: out_blk = attn[128,256] @ V2[256, ntile 128 cols]
// (scalar staging path; ~5% of runtime). Epilogue rounds ao for gemm2.
// ---------------------------------------------------------------------------
__global__ __launch_bounds__(256, 1)
void attn_pv_kernel(const float* __restrict__ qkv, const float* __restrict__ attn,
                    float* __restrict__ ao) {
    const int nb = blockIdx.x * 128, w = blockIdx.y, b = blockIdx.z;
    __shared__ float As[128][36];
    __shared__ float Bs[32][136];

    const int tid  = threadIdx.x;
    const int warp = tid >> 5, lane = tid & 31;
    const int wm = (warp & 3) << 5;
    const int wn = (warp >> 2) << 6;
    const int g  = lane >> 2, tg = lane & 3;
    const int lr = tid >> 3;
    const int lc = (tid & 7) << 2;

    const int prevblk = (w > 0) ? w - 1 : 0;
    const float* Ab = attn + ((size_t)(b * NBLK + w) * 128 + lr) * 256 + lc;

    float acc[2][8][4];
    #pragma unroll
    for (int i = 0; i < 2; i++)
        #pragma unroll
        for (int j = 0; j < 8; j++)
            #pragma unroll
            for (int q = 0; q < 4; q++) acc[i][j][q] = 0.f;

    float4 ra[4], rv[4];
    {
        #pragma unroll
        for (int i = 0; i < 4; i++)
            ra[i] = *(const float4*)(Ab + (size_t)(i * 32) * 256);
        const int jj = lr;
        const int vrow = (jj < 128) ? (b * SEQ + prevblk * 128 + jj)
                                    : (b * SEQ + w * 128 + jj - 128);
        const float* vp = qkv + (size_t)vrow * QKVN + 4096 + nb + lc;
        #pragma unroll
        for (int i = 0; i < 4; i++) rv[i] = *(const float4*)(vp + i * 32);
    }

    for (int kt = 0; kt < 256; kt += 32) {
        #pragma unroll
        for (int i = 0; i < 4; i++) {
            As[lr + i * 32][lc + 0] = ra[i].x;
            As[lr + i * 32][lc + 1] = ra[i].y;
            As[lr + i * 32][lc + 2] = ra[i].z;
            As[lr + i * 32][lc + 3] = ra[i].w;
            Bs[lr][lc + i * 32 + 0] = rv[i].x;
            Bs[lr][lc + i * 32 + 1] = rv[i].y;
            Bs[lr][lc + i * 32 + 2] = rv[i].z;
            Bs[lr][lc + i * 32 + 3] = rv[i].w;
        }
        __syncthreads();
        if (kt + 32 < 256) {
            #pragma unroll
            for (int i = 0; i < 4; i++)
                ra[i] = *(const float4*)(Ab + (size_t)(i * 32) * 256 + (kt + 32));
            const int jj = kt + 32 + lr;
            const int vrow = (jj < 128) ? (b * SEQ + prevblk * 128 + jj)
                                        : (b * SEQ + w * 128 + jj - 128);
            const float* vp = qkv + (size_t)vrow * QKVN + 4096 + nb + lc;
            #pragma unroll
            for (int i = 0; i < 4; i++) rv[i] = *(const float4*)(vp + i * 32);
        }
        #pragma unroll
        for (int ks = 0; ks < 4; ks++) {
            const int k0 = ks * 8;
            float a[2][4], bb[8][2];
            #pragma unroll
            for (int mf = 0; mf < 2; mf++) {
                const int r = wm + mf * 16 + g;
                a[mf][0] = As[r][k0 + tg];
                a[mf][1] = As[r + 8][k0 + tg];
                a[mf][2] = As[r][k0 + tg + 4];
                a[mf][3] = As[r + 8][k0 + tg + 4];
            }
            #pragma unroll
            for (int nf = 0; nf < 8; nf++) {
                const int n = wn + nf * 8 + g;
                bb[nf][0] = Bs[k0 + tg][n];
                bb[nf][1] = Bs[k0 + tg + 4][n];
            }
            #pragma unroll
            for (int mf = 0; mf < 2; mf++)
                #pragma unroll
                for (int nf = 0; nf < 8; nf++)
                    mma_tf32(acc[mf][nf][0], acc[mf][nf][1], acc[mf][nf][2], acc[mf][nf][3],
                             a[mf][0], a[mf][1], a[mf][2], a[mf][3],
                             bb[nf][0], bb[nf][1]);
        }
        __syncthreads();
    }

    #pragma unroll
    for (int mf = 0; mf < 2; mf++) {
        #pragma unroll
        for (int nf = 0; nf < 8; nf++) {
            const int row = b * SEQ + w * 128 + wm + mf * 16 + g;
            const int col = nb + wn + nf * 8 + (tg << 1);
            *(float2*)(ao + (size_t)row * DIM + col) =
                make_float2(cvt_tf32(acc[mf][nf][0]), cvt_tf32(acc[mf][nf][1]));
            *(float2*)(ao + (size_t)(row + 8) * DIM + col) =
                make_float2(cvt_tf32(acc[mf][nf][2]), cvt_tf32(acc[mf][nf][3]));
        }
    }
}

// ---------------------------------------------------------------------------
// elementwise tf32 pre-round
// ---------------------------------------------------------------------------
__global__ __launch_bounds__(256)
void round_tf32_kernel(const float4* __restrict__ in, float4* __restrict__ out, int n4) {
    int i = blockIdx.x * blockDim.x + threadIdx.x;
    if (i < n4) {
        float4 v = in[i];
        v.x = cvt_tf32(v.x); v.y = cvt_tf32(v.y);
        v.z = cvt_tf32(v.z); v.w = cvt_tf32(v.w);
        out[i] = v;
    }
}

// ---------------------------------------------------------------------------
// launch
// ---------------------------------------------------------------------------
extern "C" void kernel_launch(void* const* d_in, const int* in_sizes, int n_in,
                              void* d_out, int out_size) {
    const float* x      = (const float*)d_in[0];  // [2, 8192, 2048]
    const float* w_attn = (const float*)d_in[1];  // [6144, 2048]
    const float* w_o    = (const float*)d_in[2];  // [2048, 2048]
    float* out = (float*)d_out;

    float *qkv, *attn, *ao, *xr, *war, *wor;
    cudaGetSymbolAddress((void**)&qkv, g_qkv);
    cudaGetSymbolAddress((void**)&attn, g_attn);
    cudaGetSymbolAddress((void**)&ao, g_ao);
    cudaGetSymbolAddress((void**)&xr, g_xr);
    cudaGetSymbolAddress((void**)&war, g_war);
    cudaGetSymbolAddress((void**)&wor, g_wor);

    cudaFuncSetAttribute(gemm_nt_kernel,
                         cudaFuncAttributeMaxDynamicSharedMemorySize, GEMM_SMEM);
    cudaFuncSetAttribute(attn_sim_kernel,
                         cudaFuncAttributeMaxDynamicSharedMemorySize, GEMM_SMEM);

    // pre-round inputs (idempotent, ~50us)
    {
        int n4;
        n4 = ROWS * DIM / 4;
        round_tf32_kernel<<<(n4 + 255) / 256, 256>>>((const float4*)x, (float4*)xr, n4);
        n4 = QKVN * DIM / 4;
        round_tf32_kernel<<<(n4 + 255) / 256, 256>>>((const float4*)w_attn, (float4*)war, n4);
        n4 = DIM * DIM / 4;
        round_tf32_kernel<<<(n4 + 255) / 256, 256>>>((const float4*)w_o, (float4*)wor, n4);
    }

    // qkv = x @ w_attn^T : [16384, 6144] (rounded output)
    gemm_nt_kernel<<<dim3(QKVN / 128, ROWS / 128), 256, GEMM_SMEM>>>(
        xr, war, qkv, DIM, DIM, QKVN, DIM, 1);
    // sim -> masked relu^2 attn weights (rounded output)
    attn_sim_kernel<<<dim3(2, NBLK, BATCH), 256, GEMM_SMEM>>>(qkv, attn);
    // out_blk = attn @ V2 (rounded output)
    attn_pv_kernel<<<dim3(DIM / 128, NBLK, BATCH), 256>>>(qkv, attn, ao);
    // final = ao @ w_o^T (full fp32 output)
    gemm_nt_kernel<<<dim3(DIM / 128, ROWS / 128), 256, GEMM_SMEM>>>(
        ao, wor, out, DIM, DIM, DIM, DIM, 0);
}

// round 5
// speedup vs baseline: 1.4723x; 1.0106x over previous
#include <cuda_runtime.h>
#include <cstdint>

// Problem constants: B=2, T=8192, D=2048, W=128
#define BATCH 2
#define SEQ   8192
#define DIM   2048
#define WIN   128
#define NBLK  64
#define ROWS  16384
#define QKVN  6144

// Scratch (device globals: the sanctioned alloc-free workaround)
__device__ float g_qkv[(size_t)ROWS * QKVN];                 // rounded tf32 values
__device__ float g_attn[(size_t)BATCH * NBLK * 128 * 256];   // rounded tf32 values
__device__ float g_ao[(size_t)ROWS * DIM];                   // rounded tf32 values
__device__ float g_xr[(size_t)ROWS * DIM];                   // rounded x
__device__ float g_war[(size_t)QKVN * DIM];                  // rounded w_attn
__device__ float g_wor[(size_t)DIM * DIM];                   // rounded w_o

// ---------------------------------------------------------------------------
// helpers
// ---------------------------------------------------------------------------
__device__ __forceinline__ uint32_t smem_u32(const void* p) {
    uint32_t a;
    asm("{ .reg .u64 t; cvta.to.shared.u64 t, %1; cvt.u32.u64 %0, t; }" : "=r"(a) : "l"(p));
    return a;
}
__device__ __forceinline__ float cvt_tf32(float x) {
    uint32_t u;
    asm("cvt.rna.tf32.f32 %0, %1;" : "=r"(u) : "f"(x));
    return __uint_as_float(u);
}

__device__ __forceinline__ void mma_tf32u(float& d0, float& d1, float& d2, float& d3,
                                          uint32_t a0, uint32_t a1, uint32_t a2, uint32_t a3,
                                          uint32_t b0, uint32_t b1) {
    asm volatile(
        "mma.sync.aligned.m16n8k8.row.col.f32.tf32.tf32.f32 "
        "{%0,%1,%2,%3}, {%4,%5,%6,%7}, {%8,%9}, {%0,%1,%2,%3};\n"
        : "+f"(d0), "+f"(d1), "+f"(d2), "+f"(d3)
        : "r"(a0), "r"(a1), "r"(a2), "r"(a3), "r"(b0), "r"(b1));
}
__device__ __forceinline__ void mma_tf32(float& d0, float& d1, float& d2, float& d3,
                                         float a0, float a1, float a2, float a3,
                                         float b0, float b1) {
    mma_tf32u(d0, d1, d2, d3,
              __float_as_uint(a0), __float_as_uint(a1),
              __float_as_uint(a2), __float_as_uint(a3),
              __float_as_uint(b0), __float_as_uint(b1));
}

#define LDSM_X4(r0, r1, r2, r3, addr)                                          \
    asm volatile("ldmatrix.sync.aligned.m8n8.x4.shared.b16 {%0,%1,%2,%3}, [%4];" \
                 : "=r"(r0), "=r"(r1), "=r"(r2), "=r"(r3) : "r"(addr))

#define CP_ASYNC16(dst, src)                                                   \
    asm volatile("cp.async.cg.shared.global [%0], [%1], 16;"                   \
                 :: "r"(dst), "l"(src) : "memory")
#define CP_COMMIT() asm volatile("cp.async.commit_group;" ::: "memory")
#define CP_WAIT1()  asm volatile("cp.async.wait_group 1;" ::: "memory")

// Per-stage SMEM geometry (floats): A 128x36 + B 128x36 per stage, 3 stages.
// Row stride 144B keeps ldmatrix 8-row groups on distinct 16B sub-banks.
#define MAT_B     18432                 // bytes per matrix per stage
#define STAGE_B   36864                 // bytes per stage (A + B)
#define NSTAGE    3
#define GEMM_SMEM (NSTAGE * STAGE_B)    // 110592 B; x2 CTAs = 216KB <= 228KB

// ---------------------------------------------------------------------------
// NT GEMM: C[M,N] = A[M,K] @ B[N,K]^T. Inputs pre-rounded to tf32 values.
// 3-stage cp.async pipeline, ONE __syncthreads per K-tile, 128x128 CTA tile,
// 256 threads, 2 CTAs/SM.
// ---------------------------------------------------------------------------
__global__ __launch_bounds__(256, 2)
void gemm_nt_kernel(const float* __restrict__ A, const float* __restrict__ B,
                    float* __restrict__ C, int lda, int ldb, int N, int K,
                    int round_out) {
    extern __shared__ __align__(128) float smem[];
    const uint32_t smem_base = smem_u32(smem);

    const int tid  = threadIdx.x;
    const int warp = tid >> 5, lane = tid & 31;
    const int wm = (warp & 3) << 5;
    const int wn = (warp >> 2) << 6;
    const int g  = lane >> 2, tg = lane & 3;
    const int lr = tid >> 3;          // copy row 0..31
    const int c4 = tid & 7;           // copy 16B-chunk 0..7

    // ldmatrix lane addresses (stage 0 bases)
    const int sel = lane >> 3;
    const int i8  = lane & 7;
    uint32_t a_addr[2], b_addr[4];
    #pragma unroll
    for (int mf = 0; mf < 2; mf++) {
        const int row = wm + 16 * mf + (sel & 1) * 8 + i8;
        a_addr[mf] = smem_base + (uint32_t)(row * 36 + (sel >> 1) * 4) * 4;
    }
    #pragma unroll
    for (int np = 0; np < 4; np++) {
        const int row = wn + 8 * (2 * np + (sel >> 1)) + i8;
        b_addr[np] = smem_base + MAT_B + (uint32_t)(row * 36) * 4 + (sel & 1) * 16;
    }

    const float* Ab = A + (size_t)(blockIdx.y * 128 + lr) * lda + c4 * 4;
    const float* Bb = B + (size_t)(blockIdx.x * 128 + lr) * ldb + c4 * 4;
    const uint32_t dA = smem_base + (uint32_t)(lr * 36 + c4 * 4) * 4;
    const uint32_t dB = smem_base + MAT_B + (uint32_t)(lr * 36 + c4 * 4) * 4;

    float acc[2][8][4];
    #pragma unroll
    for (int i = 0; i < 2; i++)
        #pragma unroll
        for (int j = 0; j < 8; j++)
            #pragma unroll
            for (int q = 0; q < 4; q++) acc[i][j][q] = 0.f;

    const int NT = K >> 5;

    // prologue: stages 0, 1
    #pragma unroll
    for (int s = 0; s < 2; s++) {
        const uint32_t o = (uint32_t)s * STAGE_B;
        const float* An = Ab + s * 32;
        const float* Bn = Bb + s * 32;
        #pragma unroll
        for (int j = 0; j < 4; j++) {
            CP_ASYNC16(dA + o + j * (32 * 144), An + (size_t)(j * 32) * lda);
            CP_ASYNC16(dB + o + j * (32 * 144), Bn + (size_t)(j * 32) * ldb);
        }
        CP_COMMIT();
    }

    uint32_t af[2][4], bf[4][4];
    int s_cur = 0, s_nxt = 2;

    for (int it = 0; it < NT; it++) {
        CP_WAIT1();            // stage `it` resident (<=1 group pending)
        __syncthreads();       // all warps done consuming stage `it-1`

        // issue loads for stage it+2 into buffer (it-1)%3 (freed by the sync)
        if (it + 2 < NT) {
            const uint32_t o = (uint32_t)s_nxt * STAGE_B;
            const float* An = Ab + (it + 2) * 32;
            const float* Bn = Bb + (it + 2) * 32;
            #pragma unroll
            for (int j = 0; j < 4; j++) {
                CP_ASYNC16(dA + o + j * (32 * 144), An + (size_t)(j * 32) * lda);
                CP_ASYNC16(dB + o + j * (32 * 144), Bn + (size_t)(j * 32) * ldb);
            }
        }
        CP_COMMIT();           // commit every iter (possibly empty) to keep counts aligned

        const uint32_t so = (uint32_t)s_cur * STAGE_B;
        #pragma unroll
        for (int ks = 0; ks < 4; ks++) {
            const uint32_t ko = so + (uint32_t)ks * 32;
            #pragma unroll
            for (int mf = 0; mf < 2; mf++)
                LDSM_X4(af[mf][0], af[mf][1], af[mf][2], af[mf][3], a_addr[mf] + ko);
            #pragma unroll
            for (int np = 0; np < 4; np++)
                LDSM_X4(bf[np][0], bf[np][1], bf[np][2], bf[np][3], b_addr[np] + ko);
            #pragma unroll
            for (int mf = 0; mf < 2; mf++)
                #pragma unroll
                for (int np = 0; np < 4; np++) {
                    mma_tf32u(acc[mf][2 * np + 0][0], acc[mf][2 * np + 0][1],
                              acc[mf][2 * np + 0][2], acc[mf][2 * np + 0][3],
                              af[mf][0], af[mf][1], af[mf][2], af[mf][3],
                              bf[np][0], bf[np][1]);
                    mma_tf32u(acc[mf][2 * np + 1][0], acc[mf][2 * np + 1][1],
                              acc[mf][2 * np + 1][2], acc[mf][2 * np + 1][3],
                              af[mf][0], af[mf][1], af[mf][2], af[mf][3],
                              bf[np][2], bf[np][3]);
                }
        }
        s_cur = (s_cur == 2) ? 0 : s_cur + 1;
        s_nxt = (s_nxt == 2) ? 0 : s_nxt + 1;
    }

    #pragma unroll
    for (int mf = 0; mf < 2; mf++) {
        #pragma unroll
        for (int nf = 0; nf < 8; nf++) {
            const int row = blockIdx.y * 128 + wm + mf * 16 + g;
            const int col = blockIdx.x * 128 + wn + nf * 8 + (tg << 1);
            float2 v0 = make_float2(acc[mf][nf][0], acc[mf][nf][1]);
            float2 v1 = make_float2(acc[mf][nf][2], acc[mf][nf][3]);
            if (round_out) {
                v0.x = cvt_tf32(v0.x); v0.y = cvt_tf32(v0.y);
                v1.x = cvt_tf32(v1.x); v1.y = cvt_tf32(v1.y);
            }
            *(float2*)(C + (size_t)row * N + col) = v0;
            *(float2*)(C + (size_t)(row + 8) * N + col) = v1;
        }
    }
}

// ---------------------------------------------------------------------------
// sim kernel: per (b,w,half) 128x128 QK^T over K=2048, mask + 1/W + relu^2.
// Same 3-stage pipeline.
// ---------------------------------------------------------------------------
__global__ __launch_bounds__(256, 2)
void attn_sim_kernel(const float* __restrict__ qkv, float* __restrict__ attnOut) {
    extern __shared__ __align__(128) float smem[];
    const uint32_t smem_base = smem_u32(smem);
    const int half = blockIdx.x, w = blockIdx.y, b = blockIdx.z;

    const int tid  = threadIdx.x;
    const int warp = tid >> 5, lane = tid & 31;
    const int wm = (warp & 3) << 5;
    const int wn = (warp >> 2) << 6;
    const int g  = lane >> 2, tg = lane & 3;
    const int lr = tid >> 3;
    const int c4 = tid & 7;

    const int sel = lane >> 3;
    const int i8  = lane & 7;
    uint32_t a_addr[2], b_addr[4];
    #pragma unroll
    for (int mf = 0; mf < 2; mf++) {
        const int row = wm + 16 * mf + (sel & 1) * 8 + i8;
        a_addr[mf] = smem_base + (uint32_t)(row * 36 + (sel >> 1) * 4) * 4;
    }
    #pragma unroll
    for (int np = 0; np < 4; np++) {
        const int row = wn + 8 * (2 * np + (sel >> 1)) + i8;
        b_addr[np] = smem_base + MAT_B + (uint32_t)(row * 36) * 4 + (sel & 1) * 16;
    }

    const int kblk = (half == 0) ? (w > 0 ? w - 1 : 0) : w;
    const float* Ab = qkv + (size_t)(b * SEQ + w * 128 + lr) * QKVN + c4 * 4;
    const float* Bb = qkv + (size_t)(b * SEQ + kblk * 128 + lr) * QKVN + 2048 + c4 * 4;
    const uint32_t dA = smem_base + (uint32_t)(lr * 36 + c4 * 4) * 4;
    const uint32_t dB = smem_base + MAT_B + (uint32_t)(lr * 36 + c4 * 4) * 4;

    float acc[2][8][4];
    #pragma unroll
    for (int i = 0; i < 2; i++)
        #pragma unroll
        for (int j = 0; j < 8; j++)
            #pragma unroll
            for (int q = 0; q < 4; q++) acc[i][j][q] = 0.f;

    const int NT = DIM >> 5;

    #pragma unroll
    for (int s = 0; s < 2; s++) {
        const uint32_t o = (uint32_t)s * STAGE_B;
        const float* An = Ab + s * 32;
        const float* Bn = Bb + s * 32;
        #pragma unroll
        for (int j = 0; j < 4; j++) {
            CP_ASYNC16(dA + o + j * (32 * 144), An + (size_t)(j * 32) * QKVN);
            CP_ASYNC16(dB + o + j * (32 * 144), Bn + (size_t)(j * 32) * QKVN);
        }
        CP_COMMIT();
    }

    uint32_t af[2][4], bf[4][4];
    int s_cur = 0, s_nxt = 2;

    for (int it = 0; it < NT; it++) {
        CP_WAIT1();
        __syncthreads();

        if (it + 2 < NT) {
            const uint32_t o = (uint32_t)s_nxt * STAGE_B;
            const float* An = Ab + (it + 2) * 32;
            const float* Bn = Bb + (it + 2) * 32;
            #pragma unroll
            for (int j = 0; j < 4; j++) {
                CP_ASYNC16(dA + o + j * (32 * 144), An + (size_t)(j * 32) * QKVN);
                CP_ASYNC16(dB + o + j * (32 * 144), Bn + (size_t)(j * 32) * QKVN);
            }
        }
        CP_COMMIT();

        const uint32_t so = (uint32_t)s_cur * STAGE_B;
        #pragma unroll
        for (int ks = 0; ks < 4; ks++) {
            const uint32_t ko = so + (uint32_t)ks * 32;
            #pragma unroll
            for (int mf = 0; mf < 2; mf++)
                LDSM_X4(af[mf][0], af[mf][1], af[mf][2], af[mf][3], a_addr[mf] + ko);
            #pragma unroll
            for (int np = 0; np < 4; np++)
                LDSM_X4(bf[np][0], bf[np][1], bf[np][2], bf[np][3], b_addr[np] + ko);
            #pragma unroll
            for (int mf = 0; mf < 2; mf++)
                #pragma unroll
                for (int np = 0; np < 4; np++) {
                    mma_tf32u(acc[mf][2 * np + 0][0], acc[mf][2 * np + 0][1],
                              acc[mf][2 * np + 0][2], acc[mf][2 * np + 0][3],
                              af[mf][0], af[mf][1], af[mf][2], af[mf][3],
                              bf[np][0], bf[np][1]);
                    mma_tf32u(acc[mf][2 * np + 1][0], acc[mf][2 * np + 1][1],
                              acc[mf][2 * np + 1][2], acc[mf][2 * np + 1][3],
                              af[mf][0], af[mf][1], af[mf][2], af[mf][3],
                              bf[np][2], bf[np][3]);
                }
        }
        s_cur = (s_cur == 2) ? 0 : s_cur + 1;
        s_nxt = (s_nxt == 2) ? 0 : s_nxt + 1;
    }

    const bool halfvalid = (half == 1) || (w > 0);
    const float inv_w = 1.0f / (float)WIN;
    float* Cb = attnOut + ((size_t)(b * NBLK + w) * 128) * 256 + half * 128;

    #pragma unroll
    for (int mf = 0; mf < 2; mf++) {
        #pragma unroll
        for (int nf = 0; nf < 8; nf++) {
            const int qi0 = wm + mf * 16 + g;
            const int kj  = wn + nf * 8 + (tg << 1);
            #pragma unroll
            for (int rr = 0; rr < 2; rr++) {
                const int qi = qi0 + rr * 8;
                float s0 = acc[mf][nf][rr * 2 + 0] * inv_w;
                float s1 = acc[mf][nf][rr * 2 + 1] * inv_w;
                bool k0 = halfvalid && ((half == 0) ? (qi <= kj)     : (qi >= kj));
                bool k1 = halfvalid && ((half == 0) ? (qi <= kj + 1) : (qi >= kj + 1));
                float r0 = k0 ? fmaxf(s0, 0.f) : 0.f;
                float r1 = k1 ? fmaxf(s1, 0.f) : 0.f;
                float2 v;
                v.x = cvt_tf32(r0 * r0);
                v.y = cvt_tf32(r1 * r1);
                *(float2*)(Cb + (size_t)qi * 256 + kj) = v;
            }
        }
    }
}

// ---------------------------------------------------------------------------
// PV kernel: out_blk = attn[128,256] @ V2[256, ntile 128 cols]
// (scalar staging path; ~5% of runtime). Epilogue rounds ao for gemm2.
// ---------------------------------------------------------------------------
__global__ __launch_bounds__(256, 1)
void attn_pv_kernel(const float* __restrict__ qkv, const float* __restrict__ attn,
                    float* __restrict__ ao) {
    const int nb = blockIdx.x * 128, w = blockIdx.y, b = blockIdx.z;
    __shared__ float As[128][36];
    __shared__ float Bs[32][136];

    const int tid  = threadIdx.x;
    const int warp = tid >> 5, lane = tid & 31;
    const int wm = (warp & 3) << 5;
    const int wn = (warp >> 2) << 6;
    const int g  = lane >> 2, tg = lane & 3;
    const int lr = tid >> 3;
    const int lc = (tid & 7) << 2;

    const int prevblk = (w > 0) ? w - 1 : 0;
    const float* Ab = attn + ((size_t)(b * NBLK + w) * 128 + lr) * 256 + lc;

    float acc[2][8][4];
    #pragma unroll
    for (int i = 0; i < 2; i++)
        #pragma unroll
        for (int j = 0; j < 8; j++)
            #pragma unroll
            for (int q = 0; q < 4; q++) acc[i][j][q] = 0.f;

    float4 ra[4], rv[4];
    {
        #pragma unroll
        for (int i = 0; i < 4; i++)
            ra[i] = *(const float4*)(Ab + (size_t)(i * 32) * 256);
        const int jj = lr;
        const int vrow = (jj < 128) ? (b * SEQ + prevblk * 128 + jj)
                                    : (b * SEQ + w * 128 + jj - 128);
        const float* vp = qkv + (size_t)vrow * QKVN + 4096 + nb + lc;
        #pragma unroll
        for (int i = 0; i < 4; i++) rv[i] = *(const float4*)(vp + i * 32);
    }

    for (int kt = 0; kt < 256; kt += 32) {
        #pragma unroll
        for (int i = 0; i < 4; i++) {
            As[lr + i * 32][lc + 0] = ra[i].x;
            As[lr + i * 32][lc + 1] = ra[i].y;
            As[lr + i * 32][lc + 2] = ra[i].z;
            As[lr + i * 32][lc + 3] = ra[i].w;
            Bs[lr][lc + i * 32 + 0] = rv[i].x;
            Bs[lr][lc + i * 32 + 1] = rv[i].y;
            Bs[lr][lc + i * 32 + 2] = rv[i].z;
            Bs[lr][lc + i * 32 + 3] = rv[i].w;
        }
        __syncthreads();
        if (kt + 32 < 256) {
            #pragma unroll
            for (int i = 0; i < 4; i++)
                ra[i] = *(const float4*)(Ab + (size_t)(i * 32) * 256 + (kt + 32));
            const int jj = kt + 32 + lr;
            const int vrow = (jj < 128) ? (b * SEQ + prevblk * 128 + jj)
                                        : (b * SEQ + w * 128 + jj - 128);
            const float* vp = qkv + (size_t)vrow * QKVN + 4096 + nb + lc;
            #pragma unroll
            for (int i = 0; i < 4; i++) rv[i] = *(const float4*)(vp + i * 32);
        }
        #pragma unroll
        for (int ks = 0; ks < 4; ks++) {
            const int k0 = ks * 8;
            float a[2][4], bb[8][2];
            #pragma unroll
            for (int mf = 0; mf < 2; mf++) {
                const int r = wm + mf * 16 + g;
                a[mf][0] = As[r][k0 + tg];
                a[mf][1] = As[r + 8][k0 + tg];
                a[mf][2] = As[r][k0 + tg + 4];
                a[mf][3] = As[r + 8][k0 + tg + 4];
            }
            #pragma unroll
            for (int nf = 0; nf < 8; nf++) {
                const int n = wn + nf * 8 + g;
                bb[nf][0] = Bs[k0 + tg][n];
                bb[nf][1] = Bs[k0 + tg + 4][n];
            }
            #pragma unroll
            for (int mf = 0; mf < 2; mf++)
                #pragma unroll
                for (int nf = 0; nf < 8; nf++)
                    mma_tf32(acc[mf][nf][0], acc[mf][nf][1], acc[mf][nf][2], acc[mf][nf][3],
                             a[mf][0], a[mf][1], a[mf][2], a[mf][3],
                             bb[nf][0], bb[nf][1]);
        }
        __syncthreads();
    }

    #pragma unroll
    for (int mf = 0; mf < 2; mf++) {
        #pragma unroll
        for (int nf = 0; nf < 8; nf++) {
            const int row = b * SEQ + w * 128 + wm + mf * 16 + g;
            const int col = nb + wn + nf * 8 + (tg << 1);
            *(float2*)(ao + (size_t)row * DIM + col) =
                make_float2(cvt_tf32(acc[mf][nf][0]), cvt_tf32(acc[mf][nf][1]));
            *(float2*)(ao + (size_t)(row + 8) * DIM + col) =
                make_float2(cvt_tf32(acc[mf][nf][2]), cvt_tf32(acc[mf][nf][3]));
        }
    }
}

// ---------------------------------------------------------------------------
// elementwise tf32 pre-round
// ---------------------------------------------------------------------------
__global__ __launch_bounds__(256)
void round_tf32_kernel(const float4* __restrict__ in, float4* __restrict__ out, int n4) {
    int i = blockIdx.x * blockDim.x + threadIdx.x;
    if (i < n4) {
        float4 v = in[i];
        v.x = cvt_tf32(v.x); v.y = cvt_tf32(v.y);
        v.z = cvt_tf32(v.z); v.w = cvt_tf32(v.w);
        out[i] = v;
    }
}

// ---------------------------------------------------------------------------
// launch
// ---------------------------------------------------------------------------
extern "C" void kernel_launch(void* const* d_in, const int* in_sizes, int n_in,
                              void* d_out, int out_size) {
    const float* x      = (const float*)d_in[0];  // [2, 8192, 2048]
    const float* w_attn = (const float*)d_in[1];  // [6144, 2048]
    const float* w_o    = (const float*)d_in[2];  // [2048, 2048]
    float* out = (float*)d_out;

    float *qkv, *attn, *ao, *xr, *war, *wor;
    cudaGetSymbolAddress((void**)&qkv, g_qkv);
    cudaGetSymbolAddress((void**)&attn, g_attn);
    cudaGetSymbolAddress((void**)&ao, g_ao);
    cudaGetSymbolAddress((void**)&xr, g_xr);
    cudaGetSymbolAddress((void**)&war, g_war);
    cudaGetSymbolAddress((void**)&wor, g_wor);

    cudaFuncSetAttribute(gemm_nt_kernel,
                         cudaFuncAttributeMaxDynamicSharedMemorySize, GEMM_SMEM);
    cudaFuncSetAttribute(attn_sim_kernel,
                         cudaFuncAttributeMaxDynamicSharedMemorySize, GEMM_SMEM);

    // pre-round inputs (idempotent)
    {
        int n4;
        n4 = ROWS * DIM / 4;
        round_tf32_kernel<<<(n4 + 255) / 256, 256>>>((const float4*)x, (float4*)xr, n4);
        n4 = QKVN * DIM / 4;
        round_tf32_kernel<<<(n4 + 255) / 256, 256>>>((const float4*)w_attn, (float4*)war, n4);
        n4 = DIM * DIM / 4;
        round_tf32_kernel<<<(n4 + 255) / 256, 256>>>((const float4*)w_o, (float4*)wor, n4);
    }

    // qkv = x @ w_attn^T : [16384, 6144] (rounded output)
    gemm_nt_kernel<<<dim3(QKVN / 128, ROWS / 128), 256, GEMM_SMEM>>>(
        xr, war, qkv, DIM, DIM, QKVN, DIM, 1);
    // sim -> masked relu^2 attn weights (rounded output)
    attn_sim_kernel<<<dim3(2, NBLK, BATCH), 256, GEMM_SMEM>>>(qkv, attn);
    // out_blk = attn @ V2 (rounded output)
    attn_pv_kernel<<<dim3(DIM / 128, NBLK, BATCH), 256>>>(qkv, attn, ao);
    // final = ao @ w_o^T (full fp32 output)
    gemm_nt_kernel<<<dim3(DIM / 128, ROWS / 128), 256, GEMM_SMEM>>>(
        ao, wor, out, DIM, DIM, DIM, DIM, 0);
}

// round 6
// speedup vs baseline: 2.6982x; 1.8326x over previous
#include <cuda_runtime.h>
#include <cuda_fp16.h>
#include <cstdint>

// Problem constants: B=2, T=8192, D=2048, W=128
#define BATCH 2
#define SEQ   8192
#define DIM   2048
#define WIN   128
#define NBLK  64
#define ROWS  16384
#define QKVN  6144

// Scratch (device globals: the sanctioned alloc-free workaround)
__device__ __half g_qkv[(size_t)ROWS * QKVN];                // fp16 qkv
__device__ float  g_attn[(size_t)BATCH * NBLK * 128 * 256];  // tf32-rounded attn
__device__ __half g_ao[(size_t)ROWS * DIM];                  // fp16 attention output
__device__ __half g_xh[(size_t)ROWS * DIM];                  // fp16 x
__device__ __half g_wah[(size_t)QKVN * DIM];                 // fp16 w_attn
__device__ __half g_woh[(size_t)DIM * DIM];                  // fp16 w_o

// ---------------------------------------------------------------------------
// helpers
// ---------------------------------------------------------------------------
__device__ __forceinline__ uint32_t smem_u32(const void* p) {
    uint32_t a;
    asm("{ .reg .u64 t; cvta.to.shared.u64 t, %1; cvt.u32.u64 %0, t; }" : "=r"(a) : "l"(p));
    return a;
}
__device__ __forceinline__ float cvt_tf32(float x) {
    uint32_t u;
    asm("cvt.rna.tf32.f32 %0, %1;" : "=r"(u) : "f"(x));
    return __uint_as_float(u);
}

// fp16 mma: m16n8k16, fp32 accumulate
__device__ __forceinline__ void mma_f16(float& d0, float& d1, float& d2, float& d3,
                                        uint32_t a0, uint32_t a1, uint32_t a2, uint32_t a3,
                                        uint32_t b0, uint32_t b1) {
    asm volatile(
        "mma.sync.aligned.m16n8k16.row.col.f32.f16.f16.f32 "
        "{%0,%1,%2,%3}, {%4,%5,%6,%7}, {%8,%9}, {%0,%1,%2,%3};\n"
        : "+f"(d0), "+f"(d1), "+f"(d2), "+f"(d3)
        : "r"(a0), "r"(a1), "r"(a2), "r"(a3), "r"(b0), "r"(b1));
}
// tf32 mma (PV kernel)
__device__ __forceinline__ void mma_tf32(float& d0, float& d1, float& d2, float& d3,
                                         float a0, float a1, float a2, float a3,
                                         float b0, float b1) {
    asm volatile(
        "mma.sync.aligned.m16n8k8.row.col.f32.tf32.tf32.f32 "
        "{%0,%1,%2,%3}, {%4,%5,%6,%7}, {%8,%9}, {%0,%1,%2,%3};\n"
        : "+f"(d0), "+f"(d1), "+f"(d2), "+f"(d3)
        : "r"(__float_as_uint(a0)), "r"(__float_as_uint(a1)),
          "r"(__float_as_uint(a2)), "r"(__float_as_uint(a3)),
          "r"(__float_as_uint(b0)), "r"(__float_as_uint(b1)));
}

#define LDSM_X4(r0, r1, r2, r3, addr)                                          \
    asm volatile("ldmatrix.sync.aligned.m8n8.x4.shared.b16 {%0,%1,%2,%3}, [%4];" \
                 : "=r"(r0), "=r"(r1), "=r"(r2), "=r"(r3) : "r"(addr))

#define CP_ASYNC16(dst, src)                                                   \
    asm volatile("cp.async.cg.shared.global [%0], [%1], 16;"                   \
                 :: "r"(dst), "l"(src) : "memory")
#define CP_COMMIT() asm volatile("cp.async.commit_group;" ::: "memory")
#define CP_WAIT1()  asm volatile("cp.async.wait_group 1;" ::: "memory")

// fp16 stage geometry: K-tile = 64 halves. Row = 64 halves + 8 pad = 144B.
// Per matrix 128*144 = 18432B; stage (A+B) = 36864B; 3 stages = 110592B.
#define ROW_B     144
#define MAT_B     18432
#define STAGE_B   36864
#define NSTAGE    3
#define GEMM_SMEM (NSTAGE * STAGE_B)

// ---------------------------------------------------------------------------
// fp16 NT GEMM: C[M,N] = A[M,K] @ B[N,K]^T, half inputs, fp32 accum.
// 3-stage cp.async pipeline, one barrier per K-tile(64), 128x128 CTA tile,
// 256 threads, 2 CTAs/SM.
// ---------------------------------------------------------------------------
__global__ __launch_bounds__(256, 2)
void gemm_h_kernel(const __half* __restrict__ A, const __half* __restrict__ B,
                   void* __restrict__ Cout, int lda, int ldb, int N, int K,
                   int out_half) {
    extern __shared__ __align__(128) char smem[];
    const uint32_t smem_base = smem_u32(smem);

    const int tid  = threadIdx.x;
    const int warp = tid >> 5, lane = tid & 31;
    const int wm = (warp & 3) << 5;
    const int wn = (warp >> 2) << 6;
    const int g  = lane >> 2, tg = lane & 3;
    const int lr = tid >> 3;          // copy row 0..31
    const int c4 = tid & 7;           // copy 16B-chunk 0..7

    const int sel = lane >> 3;
    const int i8  = lane & 7;
    // A fragment addresses: matrices [mrow, mrow+8] x [k0, k8]
    uint32_t a_addr[2], b_addr[4];
    #pragma unroll
    for (int mf = 0; mf < 2; mf++) {
        const int row = wm + 16 * mf + (sel & 1) * 8 + i8;
        a_addr[mf] = smem_base + (uint32_t)row * ROW_B + (sel >> 1) * 16;
    }
    // B fragment addresses: matrices [n0..7 k0],[n0..7 k8],[n8..15 k0],[n8..15 k8]
    #pragma unroll
    for (int np = 0; np < 4; np++) {
        const int row = wn + np * 16 + (sel >> 1) * 8 + i8;
        b_addr[np] = smem_base + MAT_B + (uint32_t)row * ROW_B + (sel & 1) * 16;
    }

    const __half* Ab = A + (size_t)(blockIdx.y * 128 + lr) * lda + c4 * 8;
    const __half* Bb = B + (size_t)(blockIdx.x * 128 + lr) * ldb + c4 * 8;
    const uint32_t dA = smem_base + (uint32_t)lr * ROW_B + c4 * 16;
    const uint32_t dB = smem_base + MAT_B + (uint32_t)lr * ROW_B + c4 * 16;

    float acc[2][8][4];
    #pragma unroll
    for (int i = 0; i < 2; i++)
        #pragma unroll
        for (int j = 0; j < 8; j++)
            #pragma unroll
            for (int q = 0; q < 4; q++) acc[i][j][q] = 0.f;

    const int NT = K >> 6;   // K-tiles of 64

    // prologue: stages 0, 1
    #pragma unroll
    for (int s = 0; s < 2; s++) {
        const uint32_t o = (uint32_t)s * STAGE_B;
        const __half* An = Ab + s * 64;
        const __half* Bn = Bb + s * 64;
        #pragma unroll
        for (int j = 0; j < 4; j++) {
            CP_ASYNC16(dA + o + j * (32 * ROW_B), An + (size_t)(j * 32) * lda);
            CP_ASYNC16(dB + o + j * (32 * ROW_B), Bn + (size_t)(j * 32) * ldb);
        }
        CP_COMMIT();
    }

    uint32_t af[2][4], bf[4][4];
    int s_cur = 0, s_nxt = 2;

    for (int it = 0; it < NT; it++) {
        CP_WAIT1();
        __syncthreads();

        if (it + 2 < NT) {
            const uint32_t o = (uint32_t)s_nxt * STAGE_B;
            const __half* An = Ab + (it + 2) * 64;
            const __half* Bn = Bb + (it + 2) * 64;
            #pragma unroll
            for (int j = 0; j < 4; j++) {
                CP_ASYNC16(dA + o + j * (32 * ROW_B), An + (size_t)(j * 32) * lda);
                CP_ASYNC16(dB + o + j * (32 * ROW_B), Bn + (size_t)(j * 32) * ldb);
            }
        }
        CP_COMMIT();

        const uint32_t so = (uint32_t)s_cur * STAGE_B;
        #pragma unroll
        for (int ks = 0; ks < 4; ks++) {          // 4 x k16 steps
            const uint32_t ko = so + (uint32_t)ks * 32;   // 16 halves = 32B
            #pragma unroll
            for (int mf = 0; mf < 2; mf++)
                LDSM_X4(af[mf][0], af[mf][1], af[mf][2], af[mf][3], a_addr[mf] + ko);
            #pragma unroll
            for (int np = 0; np < 4; np++)
                LDSM_X4(bf[np][0], bf[np][1], bf[np][2], bf[np][3], b_addr[np] + ko);
            #pragma unroll
            for (int mf = 0; mf < 2; mf++)
                #pragma unroll
                for (int np = 0; np < 4; np++) {
                    mma_f16(acc[mf][2 * np + 0][0], acc[mf][2 * np + 0][1],
                            acc[mf][2 * np + 0][2], acc[mf][2 * np + 0][3],
                            af[mf][0], af[mf][1], af[mf][2], af[mf][3],
                            bf[np][0], bf[np][1]);
                    mma_f16(acc[mf][2 * np + 1][0], acc[mf][2 * np + 1][1],
                            acc[mf][2 * np + 1][2], acc[mf][2 * np + 1][3],
                            af[mf][0], af[mf][1], af[mf][2], af[mf][3],
                            bf[np][2], bf[np][3]);
                }
        }
        s_cur = (s_cur == 2) ? 0 : s_cur + 1;
        s_nxt = (s_nxt == 2) ? 0 : s_nxt + 1;
    }

    #pragma unroll
    for (int mf = 0; mf < 2; mf++) {
        #pragma unroll
        for (int nf = 0; nf < 8; nf++) {
            const int row = blockIdx.y * 128 + wm + mf * 16 + g;
            const int col = blockIdx.x * 128 + wn + nf * 8 + (tg << 1);
            if (out_half) {
                __half* C = (__half*)Cout;
                *(__half2*)(C + (size_t)row * N + col) =
                    __floats2half2_rn(acc[mf][nf][0], acc[mf][nf][1]);
                *(__half2*)(C + (size_t)(row + 8) * N + col) =
                    __floats2half2_rn(acc[mf][nf][2], acc[mf][nf][3]);
            } else {
                float* C = (float*)Cout;
                *(float2*)(C + (size_t)row * N + col) =
                    make_float2(acc[mf][nf][0], acc[mf][nf][1]);
                *(float2*)(C + (size_t)(row + 8) * N + col) =
                    make_float2(acc[mf][nf][2], acc[mf][nf][3]);
            }
        }
    }
}

// ---------------------------------------------------------------------------
// sim kernel (fp16): per (b,w,half) 128x128 QK^T over K=2048, mask+1/W+relu^2.
// ---------------------------------------------------------------------------
__global__ __launch_bounds__(256, 2)
void attn_sim_kernel(const __half* __restrict__ qkv, float* __restrict__ attnOut) {
    extern __shared__ __align__(128) char smem[];
    const uint32_t smem_base = smem_u32(smem);
    const int half_ = blockIdx.x, w = blockIdx.y, b = blockIdx.z;

    const int tid  = threadIdx.x;
    const int warp = tid >> 5, lane = tid & 31;
    const int wm = (warp & 3) << 5;
    const int wn = (warp >> 2) << 6;
    const int g  = lane >> 2, tg = lane & 3;
    const int lr = tid >> 3;
    const int c4 = tid & 7;

    const int sel = lane >> 3;
    const int i8  = lane & 7;
    uint32_t a_addr[2], b_addr[4];
    #pragma unroll
    for (int mf = 0; mf < 2; mf++) {
        const int row = wm + 16 * mf + (sel & 1) * 8 + i8;
        a_addr[mf] = smem_base + (uint32_t)row * ROW_B + (sel >> 1) * 16;
    }
    #pragma unroll
    for (int np = 0; np < 4; np++) {
        const int row = wn + np * 16 + (sel >> 1) * 8 + i8;
        b_addr[np] = smem_base + MAT_B + (uint32_t)row * ROW_B + (sel & 1) * 16;
    }

    const int kblk = (half_ == 0) ? (w > 0 ? w - 1 : 0) : w;
    const __half* Ab = qkv + (size_t)(b * SEQ + w * 128 + lr) * QKVN + c4 * 8;
    const __half* Bb = qkv + (size_t)(b * SEQ + kblk * 128 + lr) * QKVN + 2048 + c4 * 8;
    const uint32_t dA = smem_base + (uint32_t)lr * ROW_B + c4 * 16;
    const uint32_t dB = smem_base + MAT_B + (uint32_t)lr * ROW_B + c4 * 16;

    float acc[2][8][4];
    #pragma unroll
    for (int i = 0; i < 2; i++)
        #pragma unroll
        for (int j = 0; j < 8; j++)
            #pragma unroll
            for (int q = 0; q < 4; q++) acc[i][j][q] = 0.f;

    const int NT = DIM >> 6;

    #pragma unroll
    for (int s = 0; s < 2; s++) {
        const uint32_t o = (uint32_t)s * STAGE_B;
        const __half* An = Ab + s * 64;
        const __half* Bn = Bb + s * 64;
        #pragma unroll
        for (int j = 0; j < 4; j++) {
            CP_ASYNC16(dA + o + j * (32 * ROW_B), An + (size_t)(j * 32) * QKVN);
            CP_ASYNC16(dB + o + j * (32 * ROW_B), Bn + (size_t)(j * 32) * QKVN);
        }
        CP_COMMIT();
    }

    uint32_t af[2][4], bf[4][4];
    int s_cur = 0, s_nxt = 2;

    for (int it = 0; it < NT; it++) {
        CP_WAIT1();
        __syncthreads();

        if (it + 2 < NT) {
            const uint32_t o = (uint32_t)s_nxt * STAGE_B;
            const __half* An = Ab + (it + 2) * 64;
            const __half* Bn = Bb + (it + 2) * 64;
            #pragma unroll
            for (int j = 0; j < 4; j++) {
                CP_ASYNC16(dA + o + j * (32 * ROW_B), An + (size_t)(j * 32) * QKVN);
                CP_ASYNC16(dB + o + j * (32 * ROW_B), Bn + (size_t)(j * 32) * QKVN);
            }
        }
        CP_COMMIT();

        const uint32_t so = (uint32_t)s_cur * STAGE_B;
        #pragma unroll
        for (int ks = 0; ks < 4; ks++) {
            const uint32_t ko = so + (uint32_t)ks * 32;
            #pragma unroll
            for (int mf = 0; mf < 2; mf++)
                LDSM_X4(af[mf][0], af[mf][1], af[mf][2], af[mf][3], a_addr[mf] + ko);
            #pragma unroll
            for (int np = 0; np < 4; np++)
                LDSM_X4(bf[np][0], bf[np][1], bf[np][2], bf[np][3], b_addr[np] + ko);
            #pragma unroll
            for (int mf = 0; mf < 2; mf++)
                #pragma unroll
                for (int np = 0; np < 4; np++) {
                    mma_f16(acc[mf][2 * np + 0][0], acc[mf][2 * np + 0][1],
                            acc[mf][2 * np + 0][2], acc[mf][2 * np + 0][3],
                            af[mf][0], af[mf][1], af[mf][2], af[mf][3],
                            bf[np][0], bf[np][1]);
                    mma_f16(acc[mf][2 * np + 1][0], acc[mf][2 * np + 1][1],
                            acc[mf][2 * np + 1][2], acc[mf][2 * np + 1][3],
                            af[mf][0], af[mf][1], af[mf][2], af[mf][3],
                            bf[np][2], bf[np][3]);
                }
        }
        s_cur = (s_cur == 2) ? 0 : s_cur + 1;
        s_nxt = (s_nxt == 2) ? 0 : s_nxt + 1;
    }

    const bool halfvalid = (half_ == 1) || (w > 0);
    const float inv_w = 1.0f / (float)WIN;
    float* Cb = attnOut + ((size_t)(b * NBLK + w) * 128) * 256 + half_ * 128;

    #pragma unroll
    for (int mf = 0; mf < 2; mf++) {
        #pragma unroll
        for (int nf = 0; nf < 8; nf++) {
            const int qi0 = wm + mf * 16 + g;
            const int kj  = wn + nf * 8 + (tg << 1);
            #pragma unroll
            for (int rr = 0; rr < 2; rr++) {
                const int qi = qi0 + rr * 8;
                float s0 = acc[mf][nf][rr * 2 + 0] * inv_w;
                float s1 = acc[mf][nf][rr * 2 + 1] * inv_w;
                bool k0 = halfvalid && ((half_ == 0) ? (qi <= kj)     : (qi >= kj));
                bool k1 = halfvalid && ((half_ == 0) ? (qi <= kj + 1) : (qi >= kj + 1));
                float r0 = k0 ? fmaxf(s0, 0.f) : 0.f;
                float r1 = k1 ? fmaxf(s1, 0.f) : 0.f;
                float2 v;
                v.x = cvt_tf32(r0 * r0);
                v.y = cvt_tf32(r1 * r1);
                *(float2*)(Cb + (size_t)qi * 256 + kj) = v;
            }
        }
    }
}

// ---------------------------------------------------------------------------
// PV kernel: out_blk = attn[128,256](f32) @ V2[256, ntile](fp16 -> f32), tf32 mma.
// Writes ao as fp16.
// ---------------------------------------------------------------------------
__global__ __launch_bounds__(256, 1)
void attn_pv_kernel(const __half* __restrict__ qkv, const float* __restrict__ attn,
                    __half* __restrict__ ao) {
    const int nb = blockIdx.x * 128, w = blockIdx.y, b = blockIdx.z;
    __shared__ float As[128][36];
    __shared__ float Bs[32][136];

    const int tid  = threadIdx.x;
    const int warp = tid >> 5, lane = tid & 31;
    const int wm = (warp & 3) << 5;
    const int wn = (warp >> 2) << 6;
    const int g  = lane >> 2, tg = lane & 3;
    const int lr = tid >> 3;
    const int lc = (tid & 7) << 2;

    const int prevblk = (w > 0) ? w - 1 : 0;
    const float* Ab = attn + ((size_t)(b * NBLK + w) * 128 + lr) * 256 + lc;

    float acc[2][8][4];
    #pragma unroll
    for (int i = 0; i < 2; i++)
        #pragma unroll
        for (int j = 0; j < 8; j++)
            #pragma unroll
            for (int q = 0; q < 4; q++) acc[i][j][q] = 0.f;

    float4 ra[4];
    __half2 rv[4][2];
    {
        #pragma unroll
        for (int i = 0; i < 4; i++)
            ra[i] = *(const float4*)(Ab + (size_t)(i * 32) * 256);
        const int jj = lr;
        const int vrow = (jj < 128) ? (b * SEQ + prevblk * 128 + jj)
                                    : (b * SEQ + w * 128 + jj - 128);
        const __half* vp = qkv + (size_t)vrow * QKVN + 4096 + nb + lc;
        #pragma unroll
        for (int i = 0; i < 4; i++) {
            rv[i][0] = *(const __half2*)(vp + i * 32);
            rv[i][1] = *(const __half2*)(vp + i * 32 + 2);
        }
    }

    for (int kt = 0; kt < 256; kt += 32) {
        #pragma unroll
        for (int i = 0; i < 4; i++) {
            As[lr + i * 32][lc + 0] = ra[i].x;
            As[lr + i * 32][lc + 1] = ra[i].y;
            As[lr + i * 32][lc + 2] = ra[i].z;
            As[lr + i * 32][lc + 3] = ra[i].w;
            float2 v0 = __half22float2(rv[i][0]);
            float2 v1 = __half22float2(rv[i][1]);
            Bs[lr][lc + i * 32 + 0] = v0.x;
            Bs[lr][lc + i * 32 + 1] = v0.y;
            Bs[lr][lc + i * 32 + 2] = v1.x;
            Bs[lr][lc + i * 32 + 3] = v1.y;
        }
        __syncthreads();
        if (kt + 32 < 256) {
            #pragma unroll
            for (int i = 0; i < 4; i++)
                ra[i] = *(const float4*)(Ab + (size_t)(i * 32) * 256 + (kt + 32));
            const int jj = kt + 32 + lr;
            const int vrow = (jj < 128) ? (b * SEQ + prevblk * 128 + jj)
                                        : (b * SEQ + w * 128 + jj - 128);
            const __half* vp = qkv + (size_t)vrow * QKVN + 4096 + nb + lc;
            #pragma unroll
            for (int i = 0; i < 4; i++) {
                rv[i][0] = *(const __half2*)(vp + i * 32);
                rv[i][1] = *(const __half2*)(vp + i * 32 + 2);
            }
        }
        #pragma unroll
        for (int ks = 0; ks < 4; ks++) {
            const int k0 = ks * 8;
            float a[2][4], bb[8][2];
            #pragma unroll
            for (int mf = 0; mf < 2; mf++) {
                const int r = wm + mf * 16 + g;
                a[mf][0] = As[r][k0 + tg];
                a[mf][1] = As[r + 8][k0 + tg];
                a[mf][2] = As[r][k0 + tg + 4];
                a[mf][3] = As[r + 8][k0 + tg + 4];
            }
            #pragma unroll
            for (int nf = 0; nf < 8; nf++) {
                const int n = wn + nf * 8 + g;
                bb[nf][0] = Bs[k0 + tg][n];
                bb[nf][1] = Bs[k0 + tg + 4][n];
            }
            #pragma unroll
            for (int mf = 0; mf < 2; mf++)
                #pragma unroll
                for (int nf = 0; nf < 8; nf++)
                    mma_tf32(acc[mf][nf][0], acc[mf][nf][1], acc[mf][nf][2], acc[mf][nf][3],
                             a[mf][0], a[mf][1], a[mf][2], a[mf][3],
                             bb[nf][0], bb[nf][1]);
        }
        __syncthreads();
    }

    #pragma unroll
    for (int mf = 0; mf < 2; mf++) {
        #pragma unroll
        for (int nf = 0; nf < 8; nf++) {
            const int row = b * SEQ + w * 128 + wm + mf * 16 + g;
            const int col = nb + wn + nf * 8 + (tg << 1);
            *(__half2*)(ao + (size_t)row * DIM + col) =
                __floats2half2_rn(acc[mf][nf][0], acc[mf][nf][1]);
            *(__half2*)(ao + (size_t)(row + 8) * DIM + col) =
                __floats2half2_rn(acc[mf][nf][2], acc[mf][nf][3]);
        }
    }
}

// ---------------------------------------------------------------------------
// elementwise fp32 -> fp16
// ---------------------------------------------------------------------------
__global__ __launch_bounds__(256)
void to_half_kernel(const float4* __restrict__ in, __half2* __restrict__ out, int n4) {
    int i = blockIdx.x * blockDim.x + threadIdx.x;
    if (i < n4) {
        float4 v = in[i];
        out[2 * i + 0] = __floats2half2_rn(v.x, v.y);
        out[2 * i + 1] = __floats2half2_rn(v.z, v.w);
    }
}

// ---------------------------------------------------------------------------
// launch
// ---------------------------------------------------------------------------
extern "C" void kernel_launch(void* const* d_in, const int* in_sizes, int n_in,
                              void* d_out, int out_size) {
    const float* x      = (const float*)d_in[0];  // [2, 8192, 2048]
    const float* w_attn = (const float*)d_in[1];  // [6144, 2048]
    const float* w_o    = (const float*)d_in[2];  // [2048, 2048]
    float* out = (float*)d_out;

    __half *qkv, *ao, *xh, *wah, *woh;
    float *attn;
    cudaGetSymbolAddress((void**)&qkv, g_qkv);
    cudaGetSymbolAddress((void**)&attn, g_attn);
    cudaGetSymbolAddress((void**)&ao, g_ao);
    cudaGetSymbolAddress((void**)&xh, g_xh);
    cudaGetSymbolAddress((void**)&wah, g_wah);
    cudaGetSymbolAddress((void**)&woh, g_woh);

    cudaFuncSetAttribute(gemm_h_kernel,
                         cudaFuncAttributeMaxDynamicSharedMemorySize, GEMM_SMEM);
    cudaFuncSetAttribute(attn_sim_kernel,
                         cudaFuncAttributeMaxDynamicSharedMemorySize, GEMM_SMEM);

    // convert inputs to fp16
    {
        int n4;
        n4 = ROWS * DIM / 4;
        to_half_kernel<<<(n4 + 255) / 256, 256>>>((const float4*)x, (__half2*)xh, n4);
        n4 = QKVN * DIM / 4;
        to_half_kernel<<<(n4 + 255) / 256, 256>>>((const float4*)w_attn, (__half2*)wah, n4);
        n4 = DIM * DIM / 4;
        to_half_kernel<<<(n4 + 255) / 256, 256>>>((const float4*)w_o, (__half2*)woh, n4);
    }

    // qkv = x @ w_attn^T : [16384, 6144] fp16 out
    gemm_h_kernel<<<dim3(QKVN / 128, ROWS / 128), 256, GEMM_SMEM>>>(
        xh, wah, qkv, DIM, DIM, QKVN, DIM, 1);
    // sim -> masked relu^2 attn weights (f32, tf32-rounded)
    attn_sim_kernel<<<dim3(2, NBLK, BATCH), 256, GEMM_SMEM>>>(qkv, attn);
    // out_blk = attn @ V2 -> ao fp16
    attn_pv_kernel<<<dim3(DIM / 128, NBLK, BATCH), 256>>>(qkv, attn, ao);
    // final = ao @ w_o^T -> fp32 out
    gemm_h_kernel<<<dim3(DIM / 128, ROWS / 128), 256, GEMM_SMEM>>>(
        ao, woh, out, DIM, DIM, DIM, DIM, 0);
}